// round 9
// baseline (speedup 1.0000x reference)
#include <cuda_runtime.h>
#include <cuda_bf16.h>

// ---------------------------------------------------------------------------
// NeuralMapCell pipeline, fp32. Round-7 + conv2 496-CTA retile + pool fused
// into dense1. Launch order keeps conv2 4th (profiled).
// Output: concat( c_t[256], r_t[256], new_mem[256*4096] )
// ---------------------------------------------------------------------------

#define H 64
#define W 64
#define UNITS 256
#define C1OC 32
#define C2OC 64
#define H2 62            // conv2 VALID output
#define HP 61            // pool output
#define FLAT (64*61*61)  // 238144
#define NPIX 4096
#define D1BLK 296
#define D1ROWS 805       // ceil(FLAT / D1BLK)
#define CTBLK 64
#define C1PITCH 36       // 32 ic + 4 pad floats per pixel (bank-spread LDS.128)
#define C1Q (NPIX*C1OC)  // 131072 floats per ic-eighth

// Scratch (device globals; no allocation allowed)
__device__ float g_c1p[8*C1Q];          // conv1 partials, [z][pixel][oc]
__device__ float g_c1[NPIX*C1OC];       // reduced conv1 output [pixel][oc]
__device__ float g_c2[C2OC*H2*H2];      // [oc][h2][w2]
__device__ float g_part1[D1BLK*128];
__device__ float g_rt[256];
__device__ float g_qt[256];
__device__ float g_st[256];
__device__ float g_scores[NPIX];
__device__ float g_expv[NPIX];
__device__ float g_invsum;
__device__ float g_partC[CTBLK*256];

// ---------------------------------------------------------------------------
// conv1: SAME 3x3, 256 -> 32 ch. Tile 4x8 px; grid (8,16,8); z = ic eighth.
// 128 threads: o4 = t&7 (oc quad), pp = t>>3 -> row = pp>>2, col0 = (pp&3)*2.
// Per ic4: 2 LDS.128 + 4 LDG.128 weights + 32 FFMA.
// ---------------------------------------------------------------------------
__global__ __launch_bounds__(128) void conv1_kernel(
    const float* __restrict__ mem, const float* __restrict__ w1)
{
    __shared__ float sa[60*C1PITCH];     // 6x10 px halo x 32 ic, ~8.6 KB
    const int bw = blockIdx.x * 8;
    const int bh = blockIdx.y * 4;
    const int zic = blockIdx.z;          // ic eighth (32 ch)
    const int t = threadIdx.x;

    for (int idx = t; idx < 60*8; idx += 128) {
        int p = idx >> 3;                // pixel 0..59
        int q = idx & 7;                 // f4 index within 32 ch
        int r = p / 10, c = p % 10;
        int h = bh + r - 1, w = bw + c - 1;
        float4 v = make_float4(0.f,0.f,0.f,0.f);
        if (h >= 0 && h < H && w >= 0 && w < W)
            v = reinterpret_cast<const float4*>(mem + (h*W + w)*UNITS + zic*32)[q];
        reinterpret_cast<float4*>(sa + p*C1PITCH)[q] = v;
    }
    __syncthreads();

    const int o4   = t & 7;
    const int pp   = t >> 3;             // 0..15
    const int row  = pp >> 2;            // 0..3
    const int col0 = (pp & 3) * 2;       // 0,2,4,6
    float4 acc0 = make_float4(0.f,0.f,0.f,0.f);
    float4 acc1 = make_float4(0.f,0.f,0.f,0.f);

    #pragma unroll
    for (int kh = 0; kh < 3; kh++) {
        #pragma unroll
        for (int kw = 0; kw < 3; kw++) {
            const float* __restrict__ wp =
                w1 + ((size_t)((kh*3 + kw)*256 + zic*32))*32 + o4*4;
            const float* __restrict__ ap0 =
                sa + ((row+kh)*10 + (col0+kw))*C1PITCH;
            const float* __restrict__ ap1 = ap0 + C1PITCH;
            #pragma unroll
            for (int ic4 = 0; ic4 < 8; ic4++) {
                float4 a0 = *reinterpret_cast<const float4*>(ap0 + ic4*4);
                float4 a1 = *reinterpret_cast<const float4*>(ap1 + ic4*4);
                float4 w0 = __ldg(reinterpret_cast<const float4*>(wp + (4*ic4+0)*32));
                float4 wa = __ldg(reinterpret_cast<const float4*>(wp + (4*ic4+1)*32));
                float4 wb = __ldg(reinterpret_cast<const float4*>(wp + (4*ic4+2)*32));
                float4 wc = __ldg(reinterpret_cast<const float4*>(wp + (4*ic4+3)*32));
                acc0.x += a0.x*w0.x + a0.y*wa.x + a0.z*wb.x + a0.w*wc.x;
                acc0.y += a0.x*w0.y + a0.y*wa.y + a0.z*wb.y + a0.w*wc.y;
                acc0.z += a0.x*w0.z + a0.y*wa.z + a0.z*wb.z + a0.w*wc.z;
                acc0.w += a0.x*w0.w + a0.y*wa.w + a0.z*wb.w + a0.w*wc.w;
                acc1.x += a1.x*w0.x + a1.y*wa.x + a1.z*wb.x + a1.w*wc.x;
                acc1.y += a1.x*w0.y + a1.y*wa.y + a1.z*wb.y + a1.w*wc.y;
                acc1.z += a1.x*w0.z + a1.y*wa.z + a1.z*wb.z + a1.w*wc.z;
                acc1.w += a1.x*w0.w + a1.y*wa.w + a1.z*wb.w + a1.w*wc.w;
            }
        }
    }
    const int pix0 = (bh + row)*W + (bw + col0);
    reinterpret_cast<float4*>(g_c1p + (size_t)zic*C1Q + (size_t)pix0*C1OC)[o4] = acc0;
    reinterpret_cast<float4*>(g_c1p + (size_t)zic*C1Q + (size_t)(pix0+1)*C1OC)[o4] = acc1;
}

// ---------------------------------------------------------------------------
// c1red: sum 8 ic-eighth partials -> g_c1. 32768 float4s.
// ---------------------------------------------------------------------------
__global__ __launch_bounds__(256) void c1red_kernel()
{
    int i = blockIdx.x * 256 + threadIdx.x;   // f4 index, 32768 total
    float4 s = make_float4(0.f,0.f,0.f,0.f);
    #pragma unroll
    for (int z = 0; z < 8; z++) {
        float4 v = reinterpret_cast<const float4*>(g_c1p + (size_t)z*C1Q)[i];
        s.x += v.x; s.y += v.y; s.z += v.z; s.w += v.w;
    }
    reinterpret_cast<float4*>(g_c1)[i] = s;
}

// ---------------------------------------------------------------------------
// conv2: VALID 3x3, 32 -> 64 ch. Tile 2x8 px; grid (8,31,2); z = oc half.
// 128 threads, 1 px/thread: o4 = t&7, pp = t>>3 -> row = pp>>3, col = pp&7.
// Per ic4: 1 LDS.128 + 4 LDG.128 + 16 FFMA.
// ---------------------------------------------------------------------------
__global__ __launch_bounds__(128) void conv2_kernel(
    const float* __restrict__ w2)
{
    __shared__ float sa[40*C1PITCH];     // 4 rows x 10 cols x 32 ic, ~5.8 KB
    const int bw = blockIdx.x * 8;
    const int bh = blockIdx.y * 2;
    const int zoc = blockIdx.z;          // oc half
    const int t = threadIdx.x;

    for (int idx = t; idx < 40*8; idx += 128) {
        int p = idx >> 3;
        int q = idx & 7;
        int r = p / 10, c = p % 10;
        int h = bh + r, w = bw + c;
        float4 v = make_float4(0.f,0.f,0.f,0.f);
        if (h < H && w < W)
            v = reinterpret_cast<const float4*>(g_c1 + (h*W + w)*C1OC)[q];
        reinterpret_cast<float4*>(sa + p*C1PITCH)[q] = v;
    }
    __syncthreads();

    const int o4  = t & 7;               // oc quad within half
    const int pp  = t >> 3;              // 0..15
    const int row = pp >> 3;             // 0..1
    const int col = pp & 7;              // 0..7
    float4 acc = make_float4(0.f,0.f,0.f,0.f);

    #pragma unroll
    for (int kh = 0; kh < 3; kh++) {
        #pragma unroll
        for (int kw = 0; kw < 3; kw++) {
            const float* __restrict__ wp =
                w2 + ((size_t)((kh*3 + kw)*32))*64 + zoc*32 + o4*4;
            const float* __restrict__ ap =
                sa + ((row+kh)*10 + (col+kw))*C1PITCH;
            #pragma unroll
            for (int ic4 = 0; ic4 < 8; ic4++) {
                float4 a  = *reinterpret_cast<const float4*>(ap + ic4*4);
                float4 w0 = __ldg(reinterpret_cast<const float4*>(wp + (4*ic4+0)*64));
                float4 wa = __ldg(reinterpret_cast<const float4*>(wp + (4*ic4+1)*64));
                float4 wb = __ldg(reinterpret_cast<const float4*>(wp + (4*ic4+2)*64));
                float4 wc = __ldg(reinterpret_cast<const float4*>(wp + (4*ic4+3)*64));
                acc.x += a.x*w0.x + a.y*wa.x + a.z*wb.x + a.w*wc.x;
                acc.y += a.x*w0.y + a.y*wa.y + a.z*wb.y + a.w*wc.y;
                acc.z += a.x*w0.z + a.y*wa.z + a.z*wb.z + a.w*wc.z;
                acc.w += a.x*w0.w + a.y*wa.w + a.z*wb.w + a.w*wc.w;
            }
        }
    }
    const int h2  = bh + row;
    const int w2i = bw + col;
    const int oc0 = zoc*32 + o4*4;
    if (h2 < H2 && w2i < H2) {
        g_c2[(size_t)(oc0+0)*(H2*H2) + h2*H2 + w2i] = acc.x;
        g_c2[(size_t)(oc0+1)*(H2*H2) + h2*H2 + w2i] = acc.y;
        g_c2[(size_t)(oc0+2)*(H2*H2) + h2*H2 + w2i] = acc.z;
        g_c2[(size_t)(oc0+3)*(H2*H2) + h2*H2 + w2i] = acc.w;
    }
}

// ---------------------------------------------------------------------------
// dense1 (pool fused): flat[i] = 0.25*sum2x2(c2) computed inline;
// partials of flat @ W1(238144x128). Per-lane float4 loads, 4-row unroll.
// ---------------------------------------------------------------------------
__global__ __launch_bounds__(256) void dense1_kernel(const float* __restrict__ W1)
{
    const int t = threadIdx.x;
    const int lane = t & 31;
    const int wid  = t >> 5;
    const int row0 = blockIdx.x * D1ROWS;
    int lim = row0 + D1ROWS;
    if (lim > FLAT) lim = FLAT;

    float4 acc = make_float4(0.f,0.f,0.f,0.f);
    for (int k = 0; k < 104; k += 4) {          // 104*8 = 832 >= 805 rows
        #pragma unroll
        for (int u = 0; u < 4; u++) {
            int i = row0 + wid + 8*(k + u);
            if (i < lim) {
                int oc = i / (HP*HP);
                int r  = i - oc*(HP*HP);
                int h  = r / HP;
                int w  = r - h*HP;
                const float* bp = g_c2 + (size_t)oc*(H2*H2) + h*H2 + w;
                float f = 0.25f * (__ldg(bp) + __ldg(bp+1) + __ldg(bp+H2) + __ldg(bp+H2+1));
                float4 wv = __ldg(reinterpret_cast<const float4*>(W1 + (size_t)i*128) + lane);
                acc.x += f*wv.x; acc.y += f*wv.y; acc.z += f*wv.z; acc.w += f*wv.w;
            }
        }
    }
    __shared__ float4 sred[256];
    sred[wid*32 + lane] = acc;
    __syncthreads();
    if (t < 32) {
        float4 s = sred[t];
        #pragma unroll
        for (int w = 1; w < 8; w++) {
            float4 v = sred[w*32 + t];
            s.x += v.x; s.y += v.y; s.z += v.z; s.w += v.w;
        }
        reinterpret_cast<float4*>(g_part1 + blockIdx.x*128)[t] = s;
    }
}

// ---------------------------------------------------------------------------
// fuse1: reduce r128; r_t = r128@W2; q_t = [in,r_t]@ctx; s_t = in@rec[:128]
// ---------------------------------------------------------------------------
__global__ __launch_bounds__(256) void fuse1_kernel(
    const float* __restrict__ inputs, const float* __restrict__ W2,
    const float* __restrict__ ctx, const float* __restrict__ rec)
{
    __shared__ float s_r128[128];
    __shared__ float s_rt[256];
    __shared__ float s_in[128];
    const int t = threadIdx.x;

    if (t < 128) {
        float a = 0.f;
        #pragma unroll 8
        for (int b = 0; b < D1BLK; b++) a += g_part1[b*128 + t];
        s_r128[t] = a;
        s_in[t] = inputs[t];
    }
    __syncthreads();

    float rt = 0.f;
    #pragma unroll 8
    for (int k = 0; k < 128; k++) rt += s_r128[k] * W2[k*256 + t];
    s_rt[t] = rt;
    g_rt[t] = rt;
    __syncthreads();

    float q = 0.f, sv = 0.f;
    #pragma unroll 8
    for (int k = 0; k < 128; k++) {
        float iv = s_in[k];
        q  += iv * ctx[k*256 + t];
        sv += iv * rec[k*256 + t];
    }
    #pragma unroll 8
    for (int k = 0; k < 256; k++)
        q += s_rt[k] * ctx[(128 + k)*256 + t];
    g_qt[t] = q;
    g_st[t] = sv;
}

// ---------------------------------------------------------------------------
// scores[p] = dot(q_t, memory[p,:])  — warp per row
// ---------------------------------------------------------------------------
__global__ __launch_bounds__(256) void scores_kernel(const float* __restrict__ mem)
{
    __shared__ float4 sq[64];
    const int t = threadIdx.x;
    if (t < 64) sq[t] = reinterpret_cast<const float4*>(g_qt)[t];
    __syncthreads();

    const int lane = t & 31;
    const int p = blockIdx.x * 8 + (t >> 5);
    const float4* mp = reinterpret_cast<const float4*>(mem + p*UNITS);
    float4 m0 = mp[lane];
    float4 m1 = mp[lane + 32];
    float4 q0 = sq[lane];
    float4 q1 = sq[lane + 32];
    float acc = m0.x*q0.x + m0.y*q0.y + m0.z*q0.z + m0.w*q0.w
              + m1.x*q1.x + m1.y*q1.y + m1.z*q1.z + m1.w*q1.w;
    #pragma unroll
    for (int o = 16; o > 0; o >>= 1)
        acc += __shfl_down_sync(0xffffffffu, acc, o);
    if (lane == 0) g_scores[p] = acc;
}

// ---------------------------------------------------------------------------
// softmax over 4096 scores (single block)
// ---------------------------------------------------------------------------
__global__ __launch_bounds__(1024) void softmax_kernel()
{
    __shared__ float red[32];
    const int t = threadIdx.x;
    float4 v = reinterpret_cast<const float4*>(g_scores)[t];
    float m = fmaxf(fmaxf(v.x, v.y), fmaxf(v.z, v.w));
    #pragma unroll
    for (int o = 16; o > 0; o >>= 1)
        m = fmaxf(m, __shfl_xor_sync(0xffffffffu, m, o));
    if ((t & 31) == 0) red[t >> 5] = m;
    __syncthreads();
    if (t < 32) {
        float mm = red[t];
        #pragma unroll
        for (int o = 16; o > 0; o >>= 1)
            mm = fmaxf(mm, __shfl_xor_sync(0xffffffffu, mm, o));
        red[t] = mm;
    }
    __syncthreads();
    const float gmax = red[0];
    __syncthreads();

    float4 e;
    e.x = expf(v.x - gmax); e.y = expf(v.y - gmax);
    e.z = expf(v.z - gmax); e.w = expf(v.w - gmax);
    reinterpret_cast<float4*>(g_expv)[t] = e;
    float s = e.x + e.y + e.z + e.w;
    #pragma unroll
    for (int o = 16; o > 0; o >>= 1)
        s += __shfl_xor_sync(0xffffffffu, s, o);
    if ((t & 31) == 0) red[t >> 5] = s;
    __syncthreads();
    if (t == 0) {
        float ss = 0.f;
        for (int i = 0; i < 32; i++) ss += red[i];
        g_invsum = 1.f / ss;
    }
}

// ---------------------------------------------------------------------------
// c_t partials: sum_p expv[p] * memory[p,:], 64 blocks of 64 rows
// ---------------------------------------------------------------------------
__global__ __launch_bounds__(256) void ctpart_kernel(const float* __restrict__ mem)
{
    const int c = threadIdx.x;
    const int base = blockIdx.x * 64;
    float acc = 0.f;
    #pragma unroll 4
    for (int p = base; p < base + 64; p++)
        acc += g_expv[p] * __ldg(mem + p*UNITS + c);
    g_partC[blockIdx.x*256 + c] = acc;
}

// ---------------------------------------------------------------------------
// Transpose memory (4096,256) -> new_mem region of out (split launches)
// ---------------------------------------------------------------------------
__global__ __launch_bounds__(256) void transpose_kernel(
    const float* __restrict__ mem, float* __restrict__ out, int yoff)
{
    __shared__ float tile[32][33];
    const int p0 = blockIdx.x * 32;
    const int c0 = (blockIdx.y + yoff) * 32;
    const int tx = threadIdx.x, ty = threadIdx.y;
    #pragma unroll
    for (int j = ty; j < 32; j += 8)
        tile[j][tx] = mem[(p0 + j)*UNITS + c0 + tx];
    __syncthreads();
    #pragma unroll
    for (int j = ty; j < 32; j += 8)
        out[512 + (size_t)(c0 + j)*NPIX + p0 + tx] = tile[tx][j];
}

// ---------------------------------------------------------------------------
// Final: reduce c_t, importances, mem update at (x,y); write c_t, r_t
// ---------------------------------------------------------------------------
__global__ __launch_bounds__(256) void final_kernel(
    const float* __restrict__ mem, const float* __restrict__ rec,
    const int* __restrict__ px, const int* __restrict__ py,
    float* __restrict__ out)
{
    __shared__ float s_st[256], s_mold[256];
    __shared__ float red[16];
    __shared__ float s_frac;
    const int c = threadIdx.x;
    const int pos = px[0]*W + py[0];

    float ct = 0.f;
    #pragma unroll 8
    for (int b = 0; b < CTBLK; b++) ct += g_partC[b*256 + c];
    ct *= g_invsum;
    float rt = g_rt[c];
    float st = g_st[c];
    s_st[c] = st;
    s_mold[c] = mem[pos*UNITS + c];
    out[c] = ct;
    out[256 + c] = rt;

    float li = st * ct;
    float gi = st * rt;
    #pragma unroll
    for (int o = 16; o > 0; o >>= 1) {
        li += __shfl_xor_sync(0xffffffffu, li, o);
        gi += __shfl_xor_sync(0xffffffffu, gi, o);
    }
    if ((c & 31) == 0) {
        red[c >> 5] = li;
        red[8 + (c >> 5)] = gi;
    }
    __syncthreads();
    if (c == 0) {
        float L = 0.f, G = 0.f;
        for (int i = 0; i < 8; i++) { L += red[i]; G += red[8 + i]; }
        s_frac = L / (L + G);
    }
    __syncthreads();

    const float frac = s_frac;
    float d = 0.f;
    #pragma unroll 8
    for (int k = 0; k < 256; k++)
        d += (s_mold[k] - s_st[k]) * __ldg(rec + (128 + k)*256 + c);
    out[512 + (size_t)c*NPIX + pos] = s_mold[c] + frac * d;
}

// ---------------------------------------------------------------------------
extern "C" void kernel_launch(void* const* d_in, const int* in_sizes, int n_in,
                              void* d_out, int out_size)
{
    const float* inputs = (const float*)d_in[0];
    const float* mem    = (const float*)d_in[1];
    const float* ck1    = (const float*)d_in[2];
    const float* ck2    = (const float*)d_in[3];
    const float* cd1    = (const float*)d_in[4];
    const float* cd2    = (const float*)d_in[5];
    const float* ctx    = (const float*)d_in[6];
    const float* rec    = (const float*)d_in[7];
    const int*   px     = (const int*)d_in[8];
    const int*   py     = (const int*)d_in[9];
    float* out = (float*)d_out;

    // Order chosen so conv2 is the 4th launch (profiled this round).
    transpose_kernel<<<dim3(NPIX / 32, 3), dim3(32, 8)>>>(mem, out, 0);
    conv1_kernel<<<dim3(8, 16, 8), 128>>>(mem, ck1);
    c1red_kernel<<<128, 256>>>();
    conv2_kernel<<<dim3(8, 31, 2), 128>>>(ck2);
    transpose_kernel<<<dim3(NPIX / 32, 3), dim3(32, 8)>>>(mem, out, 3);
    transpose_kernel<<<dim3(NPIX / 32, 2), dim3(32, 8)>>>(mem, out, 6);
    dense1_kernel<<<D1BLK, 256>>>(cd1);
    fuse1_kernel<<<1, 256>>>(inputs, cd2, ctx, rec);
    scores_kernel<<<NPIX / 8, 256>>>(mem);
    softmax_kernel<<<1, 1024>>>();
    ctpart_kernel<<<CTBLK, 256>>>(mem);
    final_kernel<<<1, 256>>>(mem, rec, px, py, out);
}

// round 10
// speedup vs baseline: 1.2261x; 1.2261x over previous
#include <cuda_runtime.h>
#include <cuda_bf16.h>

// ---------------------------------------------------------------------------
// NeuralMapCell pipeline, fp32. Round-7 base + conv2 ic-split retile
// (2px/thread ILP shape + 496 CTAs). Pool restored (fusion reverted).
// Launch order keeps conv2 4th (profiled).
// Output: concat( c_t[256], r_t[256], new_mem[256*4096] )
// ---------------------------------------------------------------------------

#define H 64
#define W 64
#define UNITS 256
#define C1OC 32
#define C2OC 64
#define H2 62            // conv2 VALID output
#define HP 61            // pool output
#define FLAT (64*61*61)  // 238144
#define NPIX 4096
#define D1BLK 296
#define D1ROWS 805       // ceil(FLAT / D1BLK)
#define CTBLK 64
#define C1PITCH 36       // 32 ic + 4 pad floats (bank-spread LDS.128)
#define C2PITCH 20       // 16 ic + 4 pad floats
#define C1Q (NPIX*C1OC)  // 131072 floats per ic-eighth

// Scratch (device globals; no allocation allowed)
__device__ float g_c1p[8*C1Q];          // conv1 partials, [z][pixel][oc]
__device__ float g_c1[NPIX*C1OC];       // reduced conv1 output [pixel][oc]
__device__ float g_c2p[2*C2OC*H2*H2];   // conv2 ic-half partials [z][oc][h][w]
__device__ float g_flat[FLAT];          // pooled activations [oc][h][w]
__device__ float g_part1[D1BLK*128];
__device__ float g_rt[256];
__device__ float g_qt[256];
__device__ float g_st[256];
__device__ float g_scores[NPIX];
__device__ float g_expv[NPIX];
__device__ float g_invsum;
__device__ float g_partC[CTBLK*256];

// ---------------------------------------------------------------------------
// conv1: SAME 3x3, 256 -> 32 ch. Tile 4x8 px; grid (8,16,8); z = ic eighth.
// 128 threads: o4 = t&7 (oc quad), pp = t>>3 -> row = pp>>2, col0 = (pp&3)*2.
// Per ic4: 2 LDS.128 + 4 LDG.128 weights + 32 FFMA (validated round 7).
// ---------------------------------------------------------------------------
__global__ __launch_bounds__(128) void conv1_kernel(
    const float* __restrict__ mem, const float* __restrict__ w1)
{
    __shared__ float sa[60*C1PITCH];     // 6x10 px halo x 32 ic, ~8.6 KB
    const int bw = blockIdx.x * 8;
    const int bh = blockIdx.y * 4;
    const int zic = blockIdx.z;          // ic eighth (32 ch)
    const int t = threadIdx.x;

    for (int idx = t; idx < 60*8; idx += 128) {
        int p = idx >> 3;                // pixel 0..59
        int q = idx & 7;                 // f4 index within 32 ch
        int r = p / 10, c = p % 10;
        int h = bh + r - 1, w = bw + c - 1;
        float4 v = make_float4(0.f,0.f,0.f,0.f);
        if (h >= 0 && h < H && w >= 0 && w < W)
            v = reinterpret_cast<const float4*>(mem + (h*W + w)*UNITS + zic*32)[q];
        reinterpret_cast<float4*>(sa + p*C1PITCH)[q] = v;
    }
    __syncthreads();

    const int o4   = t & 7;
    const int pp   = t >> 3;             // 0..15
    const int row  = pp >> 2;            // 0..3
    const int col0 = (pp & 3) * 2;       // 0,2,4,6
    float4 acc0 = make_float4(0.f,0.f,0.f,0.f);
    float4 acc1 = make_float4(0.f,0.f,0.f,0.f);

    #pragma unroll
    for (int kh = 0; kh < 3; kh++) {
        #pragma unroll
        for (int kw = 0; kw < 3; kw++) {
            const float* __restrict__ wp =
                w1 + ((size_t)((kh*3 + kw)*256 + zic*32))*32 + o4*4;
            const float* __restrict__ ap0 =
                sa + ((row+kh)*10 + (col0+kw))*C1PITCH;
            const float* __restrict__ ap1 = ap0 + C1PITCH;
            #pragma unroll
            for (int ic4 = 0; ic4 < 8; ic4++) {
                float4 a0 = *reinterpret_cast<const float4*>(ap0 + ic4*4);
                float4 a1 = *reinterpret_cast<const float4*>(ap1 + ic4*4);
                float4 w0 = __ldg(reinterpret_cast<const float4*>(wp + (4*ic4+0)*32));
                float4 wa = __ldg(reinterpret_cast<const float4*>(wp + (4*ic4+1)*32));
                float4 wb = __ldg(reinterpret_cast<const float4*>(wp + (4*ic4+2)*32));
                float4 wc = __ldg(reinterpret_cast<const float4*>(wp + (4*ic4+3)*32));
                acc0.x += a0.x*w0.x + a0.y*wa.x + a0.z*wb.x + a0.w*wc.x;
                acc0.y += a0.x*w0.y + a0.y*wa.y + a0.z*wb.y + a0.w*wc.y;
                acc0.z += a0.x*w0.z + a0.y*wa.z + a0.z*wb.z + a0.w*wc.z;
                acc0.w += a0.x*w0.w + a0.y*wa.w + a0.z*wb.w + a0.w*wc.w;
                acc1.x += a1.x*w0.x + a1.y*wa.x + a1.z*wb.x + a1.w*wc.x;
                acc1.y += a1.x*w0.y + a1.y*wa.y + a1.z*wb.y + a1.w*wc.y;
                acc1.z += a1.x*w0.z + a1.y*wa.z + a1.z*wb.z + a1.w*wc.z;
                acc1.w += a1.x*w0.w + a1.y*wa.w + a1.z*wb.w + a1.w*wc.w;
            }
        }
    }
    const int pix0 = (bh + row)*W + (bw + col0);
    reinterpret_cast<float4*>(g_c1p + (size_t)zic*C1Q + (size_t)pix0*C1OC)[o4] = acc0;
    reinterpret_cast<float4*>(g_c1p + (size_t)zic*C1Q + (size_t)(pix0+1)*C1OC)[o4] = acc1;
}

// ---------------------------------------------------------------------------
// c1red: sum 8 ic-eighth partials -> g_c1. 32768 float4s.
// ---------------------------------------------------------------------------
__global__ __launch_bounds__(256) void c1red_kernel()
{
    int i = blockIdx.x * 256 + threadIdx.x;   // f4 index, 32768 total
    float4 s = make_float4(0.f,0.f,0.f,0.f);
    #pragma unroll
    for (int z = 0; z < 8; z++) {
        float4 v = reinterpret_cast<const float4*>(g_c1p + (size_t)z*C1Q)[i];
        s.x += v.x; s.y += v.y; s.z += v.z; s.w += v.w;
    }
    reinterpret_cast<float4*>(g_c1)[i] = s;
}

// ---------------------------------------------------------------------------
// conv2: VALID 3x3, 32 -> 64 ch, output 62x62. Tile 2x8 px, ALL 64 oc;
// grid (8,31,2); z = ic half (16 ch). 128 threads:
//   o4 = t&15 (oc quad of 64), pp = t>>4 -> row = pp>>2 (0..1), col0=(pp&3)*2.
// Per ic4: 2 LDS.128 + 4 LDG.128 + 32 FFMA, dual accumulators (conv1 shape).
// ---------------------------------------------------------------------------
__global__ __launch_bounds__(128) void conv2_kernel(
    const float* __restrict__ w2)
{
    __shared__ float sa[40*C2PITCH];     // 4 rows x 10 cols x 16 ic, 3.2 KB
    const int bw = blockIdx.x * 8;
    const int bh = blockIdx.y * 2;       // by 0..30 -> rows 0..61 (=H2) exact
    const int zic = blockIdx.z;          // ic half (16 ch)
    const int t = threadIdx.x;

    for (int idx = t; idx < 40*4; idx += 128) {
        int p = idx >> 2;                // pixel 0..39
        int q = idx & 3;                 // f4 index within 16 ch
        int r = p / 10, c = p % 10;
        int h = bh + r, w = bw + c;
        float4 v = make_float4(0.f,0.f,0.f,0.f);
        if (h < H && w < W)
            v = reinterpret_cast<const float4*>(g_c1 + (h*W + w)*C1OC + zic*16)[q];
        reinterpret_cast<float4*>(sa + p*C2PITCH)[q] = v;
    }
    __syncthreads();

    const int o4   = t & 15;             // oc quad (0..15 -> 64 oc)
    const int pp   = t >> 4;             // 0..7
    const int row  = pp >> 2;            // 0..1
    const int col0 = (pp & 3) * 2;       // 0,2,4,6
    float4 acc0 = make_float4(0.f,0.f,0.f,0.f);
    float4 acc1 = make_float4(0.f,0.f,0.f,0.f);

    #pragma unroll
    for (int kh = 0; kh < 3; kh++) {
        #pragma unroll
        for (int kw = 0; kw < 3; kw++) {
            const float* __restrict__ wp =
                w2 + ((size_t)((kh*3 + kw)*32 + zic*16))*64 + o4*4;
            const float* __restrict__ ap0 =
                sa + ((row+kh)*10 + (col0+kw))*C2PITCH;
            const float* __restrict__ ap1 = ap0 + C2PITCH;
            #pragma unroll
            for (int ic4 = 0; ic4 < 4; ic4++) {
                float4 a0 = *reinterpret_cast<const float4*>(ap0 + ic4*4);
                float4 a1 = *reinterpret_cast<const float4*>(ap1 + ic4*4);
                float4 w0 = __ldg(reinterpret_cast<const float4*>(wp + (4*ic4+0)*64));
                float4 wa = __ldg(reinterpret_cast<const float4*>(wp + (4*ic4+1)*64));
                float4 wb = __ldg(reinterpret_cast<const float4*>(wp + (4*ic4+2)*64));
                float4 wc = __ldg(reinterpret_cast<const float4*>(wp + (4*ic4+3)*64));
                acc0.x += a0.x*w0.x + a0.y*wa.x + a0.z*wb.x + a0.w*wc.x;
                acc0.y += a0.x*w0.y + a0.y*wa.y + a0.z*wb.y + a0.w*wc.y;
                acc0.z += a0.x*w0.z + a0.y*wa.z + a0.z*wb.z + a0.w*wc.z;
                acc0.w += a0.x*w0.w + a0.y*wa.w + a0.z*wb.w + a0.w*wc.w;
                acc1.x += a1.x*w0.x + a1.y*wa.x + a1.z*wb.x + a1.w*wc.x;
                acc1.y += a1.x*w0.y + a1.y*wa.y + a1.z*wb.y + a1.w*wc.y;
                acc1.z += a1.x*w0.z + a1.y*wa.z + a1.z*wb.z + a1.w*wc.z;
                acc1.w += a1.x*w0.w + a1.y*wa.w + a1.z*wb.w + a1.w*wc.w;
            }
        }
    }
    const int h2  = bh + row;
    const int oc0 = o4*4;
    const size_t zb = (size_t)zic*C2OC*H2*H2;
    #pragma unroll
    for (int s = 0; s < 2; s++) {
        int w2i = bw + col0 + s;
        if (w2i < H2) {
            float4 a = s ? acc1 : acc0;
            g_c2p[zb + (size_t)(oc0+0)*(H2*H2) + h2*H2 + w2i] = a.x;
            g_c2p[zb + (size_t)(oc0+1)*(H2*H2) + h2*H2 + w2i] = a.y;
            g_c2p[zb + (size_t)(oc0+2)*(H2*H2) + h2*H2 + w2i] = a.z;
            g_c2p[zb + (size_t)(oc0+3)*(H2*H2) + h2*H2 + w2i] = a.w;
        }
    }
}

// ---------------------------------------------------------------------------
// pool: sum the two conv2 ic-half partials, 2x2 sum pool (stride 1) * 0.25
// ---------------------------------------------------------------------------
__global__ __launch_bounds__(256) void pool_kernel()
{
    int idx = blockIdx.x * 256 + threadIdx.x;
    if (idx >= FLAT) return;
    int oc = idx / (HP*HP);
    int r = idx - oc*(HP*HP);
    int h = r / HP;
    int w = r - h*HP;
    const float* b0 = g_c2p + (size_t)oc*(H2*H2) + h*H2 + w;
    const float* b1 = b0 + (size_t)C2OC*H2*H2;
    g_flat[idx] = 0.25f * ((b0[0] + b1[0]) + (b0[1] + b1[1])
                         + (b0[H2] + b1[H2]) + (b0[H2+1] + b1[H2+1]));
}

// ---------------------------------------------------------------------------
// dense1: flat(1x238144) @ W1(238144x128). Per-lane float4 loads, 4-row unroll.
// ---------------------------------------------------------------------------
__global__ __launch_bounds__(256) void dense1_kernel(const float* __restrict__ W1)
{
    const int t = threadIdx.x;
    const int lane = t & 31;
    const int wid  = t >> 5;
    const int row0 = blockIdx.x * D1ROWS;
    int lim = row0 + D1ROWS;
    if (lim > FLAT) lim = FLAT;

    float4 acc = make_float4(0.f,0.f,0.f,0.f);
    for (int k = 0; k < 104; k += 4) {          // 104*8 = 832 >= 805 rows
        #pragma unroll
        for (int u = 0; u < 4; u++) {
            int i = row0 + wid + 8*(k + u);
            if (i < lim) {
                float f = __ldg(g_flat + i);
                float4 wv = __ldg(reinterpret_cast<const float4*>(W1 + (size_t)i*128) + lane);
                acc.x += f*wv.x; acc.y += f*wv.y; acc.z += f*wv.z; acc.w += f*wv.w;
            }
        }
    }
    __shared__ float4 sred[256];
    sred[wid*32 + lane] = acc;
    __syncthreads();
    if (t < 32) {
        float4 s = sred[t];
        #pragma unroll
        for (int w = 1; w < 8; w++) {
            float4 v = sred[w*32 + t];
            s.x += v.x; s.y += v.y; s.z += v.z; s.w += v.w;
        }
        reinterpret_cast<float4*>(g_part1 + blockIdx.x*128)[t] = s;
    }
}

// ---------------------------------------------------------------------------
// fuse1: reduce r128; r_t = r128@W2; q_t = [in,r_t]@ctx; s_t = in@rec[:128]
// ---------------------------------------------------------------------------
__global__ __launch_bounds__(256) void fuse1_kernel(
    const float* __restrict__ inputs, const float* __restrict__ W2,
    const float* __restrict__ ctx, const float* __restrict__ rec)
{
    __shared__ float s_r128[128];
    __shared__ float s_rt[256];
    __shared__ float s_in[128];
    const int t = threadIdx.x;

    if (t < 128) {
        float a = 0.f;
        #pragma unroll 8
        for (int b = 0; b < D1BLK; b++) a += g_part1[b*128 + t];
        s_r128[t] = a;
        s_in[t] = inputs[t];
    }
    __syncthreads();

    float rt = 0.f;
    #pragma unroll 8
    for (int k = 0; k < 128; k++) rt += s_r128[k] * W2[k*256 + t];
    s_rt[t] = rt;
    g_rt[t] = rt;
    __syncthreads();

    float q = 0.f, sv = 0.f;
    #pragma unroll 8
    for (int k = 0; k < 128; k++) {
        float iv = s_in[k];
        q  += iv * ctx[k*256 + t];
        sv += iv * rec[k*256 + t];
    }
    #pragma unroll 8
    for (int k = 0; k < 256; k++)
        q += s_rt[k] * ctx[(128 + k)*256 + t];
    g_qt[t] = q;
    g_st[t] = sv;
}

// ---------------------------------------------------------------------------
// scores[p] = dot(q_t, memory[p,:])  — warp per row
// ---------------------------------------------------------------------------
__global__ __launch_bounds__(256) void scores_kernel(const float* __restrict__ mem)
{
    __shared__ float4 sq[64];
    const int t = threadIdx.x;
    if (t < 64) sq[t] = reinterpret_cast<const float4*>(g_qt)[t];
    __syncthreads();

    const int lane = t & 31;
    const int p = blockIdx.x * 8 + (t >> 5);
    const float4* mp = reinterpret_cast<const float4*>(mem + p*UNITS);
    float4 m0 = mp[lane];
    float4 m1 = mp[lane + 32];
    float4 q0 = sq[lane];
    float4 q1 = sq[lane + 32];
    float acc = m0.x*q0.x + m0.y*q0.y + m0.z*q0.z + m0.w*q0.w
              + m1.x*q1.x + m1.y*q1.y + m1.z*q1.z + m1.w*q1.w;
    #pragma unroll
    for (int o = 16; o > 0; o >>= 1)
        acc += __shfl_down_sync(0xffffffffu, acc, o);
    if (lane == 0) g_scores[p] = acc;
}

// ---------------------------------------------------------------------------
// softmax over 4096 scores (single block)
// ---------------------------------------------------------------------------
__global__ __launch_bounds__(1024) void softmax_kernel()
{
    __shared__ float red[32];
    const int t = threadIdx.x;
    float4 v = reinterpret_cast<const float4*>(g_scores)[t];
    float m = fmaxf(fmaxf(v.x, v.y), fmaxf(v.z, v.w));
    #pragma unroll
    for (int o = 16; o > 0; o >>= 1)
        m = fmaxf(m, __shfl_xor_sync(0xffffffffu, m, o));
    if ((t & 31) == 0) red[t >> 5] = m;
    __syncthreads();
    if (t < 32) {
        float mm = red[t];
        #pragma unroll
        for (int o = 16; o > 0; o >>= 1)
            mm = fmaxf(mm, __shfl_xor_sync(0xffffffffu, mm, o));
        red[t] = mm;
    }
    __syncthreads();
    const float gmax = red[0];
    __syncthreads();

    float4 e;
    e.x = expf(v.x - gmax); e.y = expf(v.y - gmax);
    e.z = expf(v.z - gmax); e.w = expf(v.w - gmax);
    reinterpret_cast<float4*>(g_expv)[t] = e;
    float s = e.x + e.y + e.z + e.w;
    #pragma unroll
    for (int o = 16; o > 0; o >>= 1)
        s += __shfl_xor_sync(0xffffffffu, s, o);
    if ((t & 31) == 0) red[t >> 5] = s;
    __syncthreads();
    if (t == 0) {
        float ss = 0.f;
        for (int i = 0; i < 32; i++) ss += red[i];
        g_invsum = 1.f / ss;
    }
}

// ---------------------------------------------------------------------------
// c_t partials: sum_p expv[p] * memory[p,:], 64 blocks of 64 rows
// ---------------------------------------------------------------------------
__global__ __launch_bounds__(256) void ctpart_kernel(const float* __restrict__ mem)
{
    const int c = threadIdx.x;
    const int base = blockIdx.x * 64;
    float acc = 0.f;
    #pragma unroll 4
    for (int p = base; p < base + 64; p++)
        acc += g_expv[p] * __ldg(mem + p*UNITS + c);
    g_partC[blockIdx.x*256 + c] = acc;
}

// ---------------------------------------------------------------------------
// Transpose memory (4096,256) -> new_mem region of out (split launches)
// ---------------------------------------------------------------------------
__global__ __launch_bounds__(256) void transpose_kernel(
    const float* __restrict__ mem, float* __restrict__ out, int yoff)
{
    __shared__ float tile[32][33];
    const int p0 = blockIdx.x * 32;
    const int c0 = (blockIdx.y + yoff) * 32;
    const int tx = threadIdx.x, ty = threadIdx.y;
    #pragma unroll
    for (int j = ty; j < 32; j += 8)
        tile[j][tx] = mem[(p0 + j)*UNITS + c0 + tx];
    __syncthreads();
    #pragma unroll
    for (int j = ty; j < 32; j += 8)
        out[512 + (size_t)(c0 + j)*NPIX + p0 + tx] = tile[tx][j];
}

// ---------------------------------------------------------------------------
// Final: reduce c_t, importances, mem update at (x,y); write c_t, r_t
// ---------------------------------------------------------------------------
__global__ __launch_bounds__(256) void final_kernel(
    const float* __restrict__ mem, const float* __restrict__ rec,
    const int* __restrict__ px, const int* __restrict__ py,
    float* __restrict__ out)
{
    __shared__ float s_st[256], s_mold[256];
    __shared__ float red[16];
    __shared__ float s_frac;
    const int c = threadIdx.x;
    const int pos = px[0]*W + py[0];

    float ct = 0.f;
    #pragma unroll 8
    for (int b = 0; b < CTBLK; b++) ct += g_partC[b*256 + c];
    ct *= g_invsum;
    float rt = g_rt[c];
    float st = g_st[c];
    s_st[c] = st;
    s_mold[c] = mem[pos*UNITS + c];
    out[c] = ct;
    out[256 + c] = rt;

    float li = st * ct;
    float gi = st * rt;
    #pragma unroll
    for (int o = 16; o > 0; o >>= 1) {
        li += __shfl_xor_sync(0xffffffffu, li, o);
        gi += __shfl_xor_sync(0xffffffffu, gi, o);
    }
    if ((c & 31) == 0) {
        red[c >> 5] = li;
        red[8 + (c >> 5)] = gi;
    }
    __syncthreads();
    if (c == 0) {
        float L = 0.f, G = 0.f;
        for (int i = 0; i < 8; i++) { L += red[i]; G += red[8 + i]; }
        s_frac = L / (L + G);
    }
    __syncthreads();

    const float frac = s_frac;
    float d = 0.f;
    #pragma unroll 8
    for (int k = 0; k < 256; k++)
        d += (s_mold[k] - s_st[k]) * __ldg(rec + (128 + k)*256 + c);
    out[512 + (size_t)c*NPIX + pos] = s_mold[c] + frac * d;
}

// ---------------------------------------------------------------------------
extern "C" void kernel_launch(void* const* d_in, const int* in_sizes, int n_in,
                              void* d_out, int out_size)
{
    const float* inputs = (const float*)d_in[0];
    const float* mem    = (const float*)d_in[1];
    const float* ck1    = (const float*)d_in[2];
    const float* ck2    = (const float*)d_in[3];
    const float* cd1    = (const float*)d_in[4];
    const float* cd2    = (const float*)d_in[5];
    const float* ctx    = (const float*)d_in[6];
    const float* rec    = (const float*)d_in[7];
    const int*   px     = (const int*)d_in[8];
    const int*   py     = (const int*)d_in[9];
    float* out = (float*)d_out;

    // Order chosen so conv2 is the 4th launch (profiled this round).
    transpose_kernel<<<dim3(NPIX / 32, 3), dim3(32, 8)>>>(mem, out, 0);
    conv1_kernel<<<dim3(8, 16, 8), 128>>>(mem, ck1);
    c1red_kernel<<<128, 256>>>();
    conv2_kernel<<<dim3(8, 31, 2), 128>>>(ck2);
    transpose_kernel<<<dim3(NPIX / 32, 3), dim3(32, 8)>>>(mem, out, 3);
    transpose_kernel<<<dim3(NPIX / 32, 2), dim3(32, 8)>>>(mem, out, 6);
    pool_kernel<<<(FLAT + 255) / 256, 256>>>();
    dense1_kernel<<<D1BLK, 256>>>(cd1);
    fuse1_kernel<<<1, 256>>>(inputs, cd2, ctx, rec);
    scores_kernel<<<NPIX / 8, 256>>>(mem);
    softmax_kernel<<<1, 1024>>>();
    ctpart_kernel<<<CTBLK, 256>>>(mem);
    final_kernel<<<1, 256>>>(mem, rec, px, py, out);
}

// round 12
// speedup vs baseline: 1.5612x; 1.2733x over previous
#include <cuda_runtime.h>
#include <cuda_bf16.h>

// ---------------------------------------------------------------------------
// NeuralMapCell pipeline, fp32. Round-10 + conv1 ic-split-16 + fuse1
// parallelized into 4 stages. conv1 is the 4th launch (profiled).
// Output: concat( c_t[256], r_t[256], new_mem[256*4096] )
// ---------------------------------------------------------------------------

#define H 64
#define W 64
#define UNITS 256
#define C1OC 32
#define C2OC 64
#define H2 62            // conv2 VALID output
#define HP 61            // pool output
#define FLAT (64*61*61)  // 238144
#define NPIX 4096
#define D1BLK 296
#define D1ROWS 805       // ceil(FLAT / D1BLK)
#define CTBLK 64
#define C1SPLIT 16
#define C1PITCH 20       // 16 ic + 4 pad floats (bank-spread LDS.128)
#define C2PITCH 20       // 16 ic + 4 pad floats
#define C1Q (NPIX*C1OC)  // 131072 floats per ic-slice

// Scratch (device globals; no allocation allowed)
__device__ float g_c1p[C1SPLIT*C1Q];    // conv1 partials, [z][pixel][oc]
__device__ float g_c1[NPIX*C1OC];       // reduced conv1 output [pixel][oc]
__device__ float g_c2p[2*C2OC*H2*H2];   // conv2 ic-half partials [z][oc][h][w]
__device__ float g_flat[FLAT];          // pooled activations [oc][h][w]
__device__ float g_part1[D1BLK*128];
__device__ float g_r128[128];
__device__ float g_rt[256];
__device__ float g_qpre[4*256];
__device__ float g_spre[4*256];
__device__ float g_qpart[8*256];
__device__ float g_qt[256];
__device__ float g_st[256];
__device__ float g_scores[NPIX];
__device__ float g_expv[NPIX];
__device__ float g_invsum;
__device__ float g_partC[CTBLK*256];

// ---------------------------------------------------------------------------
// conv1: SAME 3x3, 256 -> 32 ch. Tile 4x8 px; grid (8,16,16); z = 16-ic slice.
// 128 threads: o4 = t&7 (oc quad), pp = t>>3 -> row = pp>>2, col0 = (pp&3)*2.
// Per ic4: 2 LDS.128 + 4 LDG.128 weights + 32 FFMA, dual accumulators.
// ---------------------------------------------------------------------------
__global__ __launch_bounds__(128) void conv1_kernel(
    const float* __restrict__ mem, const float* __restrict__ w1)
{
    __shared__ float sa[60*C1PITCH];     // 6x10 px halo x 16 ic, 4.8 KB
    const int bw = blockIdx.x * 8;
    const int bh = blockIdx.y * 4;
    const int zic = blockIdx.z;          // ic slice (16 ch)
    const int t = threadIdx.x;

    for (int idx = t; idx < 60*4; idx += 128) {
        int p = idx >> 2;                // pixel 0..59
        int q = idx & 3;                 // f4 index within 16 ch
        int r = p / 10, c = p % 10;
        int h = bh + r - 1, w = bw + c - 1;
        float4 v = make_float4(0.f,0.f,0.f,0.f);
        if (h >= 0 && h < H && w >= 0 && w < W)
            v = reinterpret_cast<const float4*>(mem + (h*W + w)*UNITS + zic*16)[q];
        reinterpret_cast<float4*>(sa + p*C1PITCH)[q] = v;
    }
    __syncthreads();

    const int o4   = t & 7;
    const int pp   = t >> 3;             // 0..15
    const int row  = pp >> 2;            // 0..3
    const int col0 = (pp & 3) * 2;       // 0,2,4,6
    float4 acc0 = make_float4(0.f,0.f,0.f,0.f);
    float4 acc1 = make_float4(0.f,0.f,0.f,0.f);

    #pragma unroll
    for (int kh = 0; kh < 3; kh++) {
        #pragma unroll
        for (int kw = 0; kw < 3; kw++) {
            const float* __restrict__ wp =
                w1 + ((size_t)((kh*3 + kw)*256 + zic*16))*32 + o4*4;
            const float* __restrict__ ap0 =
                sa + ((row+kh)*10 + (col0+kw))*C1PITCH;
            const float* __restrict__ ap1 = ap0 + C1PITCH;
            #pragma unroll
            for (int ic4 = 0; ic4 < 4; ic4++) {
                float4 a0 = *reinterpret_cast<const float4*>(ap0 + ic4*4);
                float4 a1 = *reinterpret_cast<const float4*>(ap1 + ic4*4);
                float4 w0 = __ldg(reinterpret_cast<const float4*>(wp + (4*ic4+0)*32));
                float4 wa = __ldg(reinterpret_cast<const float4*>(wp + (4*ic4+1)*32));
                float4 wb = __ldg(reinterpret_cast<const float4*>(wp + (4*ic4+2)*32));
                float4 wc = __ldg(reinterpret_cast<const float4*>(wp + (4*ic4+3)*32));
                acc0.x += a0.x*w0.x + a0.y*wa.x + a0.z*wb.x + a0.w*wc.x;
                acc0.y += a0.x*w0.y + a0.y*wa.y + a0.z*wb.y + a0.w*wc.y;
                acc0.z += a0.x*w0.z + a0.y*wa.z + a0.z*wb.z + a0.w*wc.z;
                acc0.w += a0.x*w0.w + a0.y*wa.w + a0.z*wb.w + a0.w*wc.w;
                acc1.x += a1.x*w0.x + a1.y*wa.x + a1.z*wb.x + a1.w*wc.x;
                acc1.y += a1.x*w0.y + a1.y*wa.y + a1.z*wb.y + a1.w*wc.y;
                acc1.z += a1.x*w0.z + a1.y*wa.z + a1.z*wb.z + a1.w*wc.z;
                acc1.w += a1.x*w0.w + a1.y*wa.w + a1.z*wb.w + a1.w*wc.w;
            }
        }
    }
    const int pix0 = (bh + row)*W + (bw + col0);
    reinterpret_cast<float4*>(g_c1p + (size_t)zic*C1Q + (size_t)pix0*C1OC)[o4] = acc0;
    reinterpret_cast<float4*>(g_c1p + (size_t)zic*C1Q + (size_t)(pix0+1)*C1OC)[o4] = acc1;
}

// ---------------------------------------------------------------------------
// c1red: sum 16 ic-slice partials -> g_c1. 32768 float4s.
// ---------------------------------------------------------------------------
__global__ __launch_bounds__(256) void c1red_kernel()
{
    int i = blockIdx.x * 256 + threadIdx.x;   // f4 index, 32768 total
    float4 s = make_float4(0.f,0.f,0.f,0.f);
    #pragma unroll
    for (int z = 0; z < C1SPLIT; z++) {
        float4 v = reinterpret_cast<const float4*>(g_c1p + (size_t)z*C1Q)[i];
        s.x += v.x; s.y += v.y; s.z += v.z; s.w += v.w;
    }
    reinterpret_cast<float4*>(g_c1)[i] = s;
}

// ---------------------------------------------------------------------------
// conv2: VALID 3x3, 32 -> 64 ch. Tile 2x8 px, ALL 64 oc; grid (8,31,2);
// z = ic half (16 ch). (validated round 10: 21.1us)
// ---------------------------------------------------------------------------
__global__ __launch_bounds__(128) void conv2_kernel(
    const float* __restrict__ w2)
{
    __shared__ float sa[40*C2PITCH];     // 4 rows x 10 cols x 16 ic, 3.2 KB
    const int bw = blockIdx.x * 8;
    const int bh = blockIdx.y * 2;
    const int zic = blockIdx.z;          // ic half (16 ch)
    const int t = threadIdx.x;

    for (int idx = t; idx < 40*4; idx += 128) {
        int p = idx >> 2;
        int q = idx & 3;
        int r = p / 10, c = p % 10;
        int h = bh + r, w = bw + c;
        float4 v = make_float4(0.f,0.f,0.f,0.f);
        if (h < H && w < W)
            v = reinterpret_cast<const float4*>(g_c1 + (h*W + w)*C1OC + zic*16)[q];
        reinterpret_cast<float4*>(sa + p*C2PITCH)[q] = v;
    }
    __syncthreads();

    const int o4   = t & 15;
    const int pp   = t >> 4;
    const int row  = pp >> 2;
    const int col0 = (pp & 3) * 2;
    float4 acc0 = make_float4(0.f,0.f,0.f,0.f);
    float4 acc1 = make_float4(0.f,0.f,0.f,0.f);

    #pragma unroll
    for (int kh = 0; kh < 3; kh++) {
        #pragma unroll
        for (int kw = 0; kw < 3; kw++) {
            const float* __restrict__ wp =
                w2 + ((size_t)((kh*3 + kw)*32 + zic*16))*64 + o4*4;
            const float* __restrict__ ap0 =
                sa + ((row+kh)*10 + (col0+kw))*C2PITCH;
            const float* __restrict__ ap1 = ap0 + C2PITCH;
            #pragma unroll
            for (int ic4 = 0; ic4 < 4; ic4++) {
                float4 a0 = *reinterpret_cast<const float4*>(ap0 + ic4*4);
                float4 a1 = *reinterpret_cast<const float4*>(ap1 + ic4*4);
                float4 w0 = __ldg(reinterpret_cast<const float4*>(wp + (4*ic4+0)*64));
                float4 wa = __ldg(reinterpret_cast<const float4*>(wp + (4*ic4+1)*64));
                float4 wb = __ldg(reinterpret_cast<const float4*>(wp + (4*ic4+2)*64));
                float4 wc = __ldg(reinterpret_cast<const float4*>(wp + (4*ic4+3)*64));
                acc0.x += a0.x*w0.x + a0.y*wa.x + a0.z*wb.x + a0.w*wc.x;
                acc0.y += a0.x*w0.y + a0.y*wa.y + a0.z*wb.y + a0.w*wc.y;
                acc0.z += a0.x*w0.z + a0.y*wa.z + a0.z*wb.z + a0.w*wc.z;
                acc0.w += a0.x*w0.w + a0.y*wa.w + a0.z*wb.w + a0.w*wc.w;
                acc1.x += a1.x*w0.x + a1.y*wa.x + a1.z*wb.x + a1.w*wc.x;
                acc1.y += a1.x*w0.y + a1.y*wa.y + a1.z*wb.y + a1.w*wc.y;
                acc1.z += a1.x*w0.z + a1.y*wa.z + a1.z*wb.z + a1.w*wc.z;
                acc1.w += a1.x*w0.w + a1.y*wa.w + a1.z*wb.w + a1.w*wc.w;
            }
        }
    }
    const int h2  = bh + row;
    const int oc0 = o4*4;
    const size_t zb = (size_t)zic*C2OC*H2*H2;
    #pragma unroll
    for (int s = 0; s < 2; s++) {
        int w2i = bw + col0 + s;
        if (w2i < H2) {
            float4 a = s ? acc1 : acc0;
            g_c2p[zb + (size_t)(oc0+0)*(H2*H2) + h2*H2 + w2i] = a.x;
            g_c2p[zb + (size_t)(oc0+1)*(H2*H2) + h2*H2 + w2i] = a.y;
            g_c2p[zb + (size_t)(oc0+2)*(H2*H2) + h2*H2 + w2i] = a.z;
            g_c2p[zb + (size_t)(oc0+3)*(H2*H2) + h2*H2 + w2i] = a.w;
        }
    }
}

// ---------------------------------------------------------------------------
// pool: sum the two conv2 ic-half partials, 2x2 sum pool * 0.25
// ---------------------------------------------------------------------------
__global__ __launch_bounds__(256) void pool_kernel()
{
    int idx = blockIdx.x * 256 + threadIdx.x;
    if (idx >= FLAT) return;
    int oc = idx / (HP*HP);
    int r = idx - oc*(HP*HP);
    int h = r / HP;
    int w = r - h*HP;
    const float* b0 = g_c2p + (size_t)oc*(H2*H2) + h*H2 + w;
    const float* b1 = b0 + (size_t)C2OC*H2*H2;
    g_flat[idx] = 0.25f * ((b0[0] + b1[0]) + (b0[1] + b1[1])
                         + (b0[H2] + b1[H2]) + (b0[H2+1] + b1[H2+1]));
}

// ---------------------------------------------------------------------------
// dense1: flat(1x238144) @ W1(238144x128). Per-lane float4 loads, 4-row unroll.
// ---------------------------------------------------------------------------
__global__ __launch_bounds__(256) void dense1_kernel(const float* __restrict__ W1)
{
    const int t = threadIdx.x;
    const int lane = t & 31;
    const int wid  = t >> 5;
    const int row0 = blockIdx.x * D1ROWS;
    int lim = row0 + D1ROWS;
    if (lim > FLAT) lim = FLAT;

    float4 acc = make_float4(0.f,0.f,0.f,0.f);
    for (int k = 0; k < 104; k += 4) {          // 104*8 = 832 >= 805 rows
        #pragma unroll
        for (int u = 0; u < 4; u++) {
            int i = row0 + wid + 8*(k + u);
            if (i < lim) {
                float f = __ldg(g_flat + i);
                float4 wv = __ldg(reinterpret_cast<const float4*>(W1 + (size_t)i*128) + lane);
                acc.x += f*wv.x; acc.y += f*wv.y; acc.z += f*wv.z; acc.w += f*wv.w;
            }
        }
    }
    __shared__ float4 sred[256];
    sred[wid*32 + lane] = acc;
    __syncthreads();
    if (t < 32) {
        float4 s = sred[t];
        #pragma unroll
        for (int w = 1; w < 8; w++) {
            float4 v = sred[w*32 + t];
            s.x += v.x; s.y += v.y; s.z += v.z; s.w += v.w;
        }
        reinterpret_cast<float4*>(g_part1 + blockIdx.x*128)[t] = s;
    }
}

// ---------------------------------------------------------------------------
// fuse1a: reduce g_part1 (296x128) -> g_r128. 1024 threads, 8 slices per col.
// ---------------------------------------------------------------------------
__global__ __launch_bounds__(1024) void fuse1a_kernel()
{
    __shared__ float sred[1024];
    const int t = threadIdx.x;
    const int col = t & 127;
    const int sl  = t >> 7;              // 0..7
    float a = 0.f;
    #pragma unroll 4
    for (int b = sl*37; b < sl*37 + 37 && b < D1BLK; b++)
        a += g_part1[b*128 + col];
    sred[sl*128 + col] = a;
    __syncthreads();
    if (t < 128) {
        float s = 0.f;
        #pragma unroll
        for (int z = 0; z < 8; z++) s += sred[z*128 + t];
        g_r128[t] = s;
    }
}

// ---------------------------------------------------------------------------
// fuse1b: 9 blocks. b0: rt = r128@W2. b1-4: qpre z-partials (inputs@ctx).
// b5-8: spre z-partials (inputs@rec).
// ---------------------------------------------------------------------------
__global__ __launch_bounds__(256) void fuse1b_kernel(
    const float* __restrict__ inputs, const float* __restrict__ W2,
    const float* __restrict__ ctx, const float* __restrict__ rec)
{
    const int c = threadIdx.x;
    const int b = blockIdx.x;
    if (b == 0) {
        float rt = 0.f;
        #pragma unroll 8
        for (int k = 0; k < 128; k++)
            rt += g_r128[k] * __ldg(W2 + k*256 + c);
        g_rt[c] = rt;
    } else if (b <= 4) {
        const int z = b - 1;
        float q = 0.f;
        #pragma unroll 8
        for (int k = z*32; k < z*32 + 32; k++)
            q += __ldg(inputs + k) * __ldg(ctx + k*256 + c);
        g_qpre[z*256 + c] = q;
    } else {
        const int z = b - 5;
        float s = 0.f;
        #pragma unroll 8
        for (int k = z*32; k < z*32 + 32; k++)
            s += __ldg(inputs + k) * __ldg(rec + k*256 + c);
        g_spre[z*256 + c] = s;
    }
}

// ---------------------------------------------------------------------------
// fuse1c: 8 blocks, z-partials of rt@ctx[128:384]
// ---------------------------------------------------------------------------
__global__ __launch_bounds__(256) void fuse1c_kernel(const float* __restrict__ ctx)
{
    const int c = threadIdx.x;
    const int z = blockIdx.x;
    float q = 0.f;
    #pragma unroll 8
    for (int j = 0; j < 32; j++) {
        int k = z*32 + j;
        q += g_rt[k] * __ldg(ctx + (128 + k)*256 + c);
    }
    g_qpart[z*256 + c] = q;
}

// ---------------------------------------------------------------------------
// qsum: qt = sum(4 qpre) + sum(8 qpart); st = sum(4 spre). 1 block.
// ---------------------------------------------------------------------------
__global__ __launch_bounds__(256) void qsum_kernel()
{
    const int c = threadIdx.x;
    float q = 0.f, s = 0.f;
    #pragma unroll
    for (int z = 0; z < 4; z++) { q += g_qpre[z*256 + c]; s += g_spre[z*256 + c]; }
    #pragma unroll
    for (int z = 0; z < 8; z++) q += g_qpart[z*256 + c];
    g_qt[c] = q;
    g_st[c] = s;
}

// ---------------------------------------------------------------------------
// scores[p] = dot(q_t, memory[p,:])  — warp per row
// ---------------------------------------------------------------------------
__global__ __launch_bounds__(256) void scores_kernel(const float* __restrict__ mem)
{
    __shared__ float4 sq[64];
    const int t = threadIdx.x;
    if (t < 64) sq[t] = reinterpret_cast<const float4*>(g_qt)[t];
    __syncthreads();

    const int lane = t & 31;
    const int p = blockIdx.x * 8 + (t >> 5);
    const float4* mp = reinterpret_cast<const float4*>(mem + p*UNITS);
    float4 m0 = mp[lane];
    float4 m1 = mp[lane + 32];
    float4 q0 = sq[lane];
    float4 q1 = sq[lane + 32];
    float acc = m0.x*q0.x + m0.y*q0.y + m0.z*q0.z + m0.w*q0.w
              + m1.x*q1.x + m1.y*q1.y + m1.z*q1.z + m1.w*q1.w;
    #pragma unroll
    for (int o = 16; o > 0; o >>= 1)
        acc += __shfl_down_sync(0xffffffffu, acc, o);
    if (lane == 0) g_scores[p] = acc;
}

// ---------------------------------------------------------------------------
// softmax over 4096 scores (single block)
// ---------------------------------------------------------------------------
__global__ __launch_bounds__(1024) void softmax_kernel()
{
    __shared__ float red[32];
    const int t = threadIdx.x;
    float4 v = reinterpret_cast<const float4*>(g_scores)[t];
    float m = fmaxf(fmaxf(v.x, v.y), fmaxf(v.z, v.w));
    #pragma unroll
    for (int o = 16; o > 0; o >>= 1)
        m = fmaxf(m, __shfl_xor_sync(0xffffffffu, m, o));
    if ((t & 31) == 0) red[t >> 5] = m;
    __syncthreads();
    if (t < 32) {
        float mm = red[t];
        #pragma unroll
        for (int o = 16; o > 0; o >>= 1)
            mm = fmaxf(mm, __shfl_xor_sync(0xffffffffu, mm, o));
        red[t] = mm;
    }
    __syncthreads();
    const float gmax = red[0];
    __syncthreads();

    float4 e;
    e.x = expf(v.x - gmax); e.y = expf(v.y - gmax);
    e.z = expf(v.z - gmax); e.w = expf(v.w - gmax);
    reinterpret_cast<float4*>(g_expv)[t] = e;
    float s = e.x + e.y + e.z + e.w;
    #pragma unroll
    for (int o = 16; o > 0; o >>= 1)
        s += __shfl_xor_sync(0xffffffffu, s, o);
    if ((t & 31) == 0) red[t >> 5] = s;
    __syncthreads();
    if (t == 0) {
        float ss = 0.f;
        for (int i = 0; i < 32; i++) ss += red[i];
        g_invsum = 1.f / ss;
    }
}

// ---------------------------------------------------------------------------
// c_t partials: sum_p expv[p] * memory[p,:], 64 blocks of 64 rows
// ---------------------------------------------------------------------------
__global__ __launch_bounds__(256) void ctpart_kernel(const float* __restrict__ mem)
{
    const int c = threadIdx.x;
    const int base = blockIdx.x * 64;
    float acc = 0.f;
    #pragma unroll 4
    for (int p = base; p < base + 64; p++)
        acc += g_expv[p] * __ldg(mem + p*UNITS + c);
    g_partC[blockIdx.x*256 + c] = acc;
}

// ---------------------------------------------------------------------------
// Transpose memory (4096,256) -> new_mem region of out (split launches)
// ---------------------------------------------------------------------------
__global__ __launch_bounds__(256) void transpose_kernel(
    const float* __restrict__ mem, float* __restrict__ out, int yoff)
{
    __shared__ float tile[32][33];
    const int p0 = blockIdx.x * 32;
    const int c0 = (blockIdx.y + yoff) * 32;
    const int tx = threadIdx.x, ty = threadIdx.y;
    #pragma unroll
    for (int j = ty; j < 32; j += 8)
        tile[j][tx] = mem[(p0 + j)*UNITS + c0 + tx];
    __syncthreads();
    #pragma unroll
    for (int j = ty; j < 32; j += 8)
        out[512 + (size_t)(c0 + j)*NPIX + p0 + tx] = tile[tx][j];
}

// ---------------------------------------------------------------------------
// Final: reduce c_t, importances, mem update at (x,y); write c_t, r_t
// ---------------------------------------------------------------------------
__global__ __launch_bounds__(256) void final_kernel(
    const float* __restrict__ mem, const float* __restrict__ rec,
    const int* __restrict__ px, const int* __restrict__ py,
    float* __restrict__ out)
{
    __shared__ float s_st[256], s_mold[256];
    __shared__ float red[16];
    __shared__ float s_frac;
    const int c = threadIdx.x;
    const int pos = px[0]*W + py[0];

    float ct = 0.f;
    #pragma unroll 8
    for (int b = 0; b < CTBLK; b++) ct += g_partC[b*256 + c];
    ct *= g_invsum;
    float rt = g_rt[c];
    float st = g_st[c];
    s_st[c] = st;
    s_mold[c] = mem[pos*UNITS + c];
    out[c] = ct;
    out[256 + c] = rt;

    float li = st * ct;
    float gi = st * rt;
    #pragma unroll
    for (int o = 16; o > 0; o >>= 1) {
        li += __shfl_xor_sync(0xffffffffu, li, o);
        gi += __shfl_xor_sync(0xffffffffu, gi, o);
    }
    if ((c & 31) == 0) {
        red[c >> 5] = li;
        red[8 + (c >> 5)] = gi;
    }
    __syncthreads();
    if (c == 0) {
        float L = 0.f, G = 0.f;
        for (int i = 0; i < 8; i++) { L += red[i]; G += red[8 + i]; }
        s_frac = L / (L + G);
    }
    __syncthreads();

    const float frac = s_frac;
    float d = 0.f;
    #pragma unroll 8
    for (int k = 0; k < 256; k++)
        d += (s_mold[k] - s_st[k]) * __ldg(rec + (128 + k)*256 + c);
    out[512 + (size_t)c*NPIX + pos] = s_mold[c] + frac * d;
}

// ---------------------------------------------------------------------------
extern "C" void kernel_launch(void* const* d_in, const int* in_sizes, int n_in,
                              void* d_out, int out_size)
{
    const float* inputs = (const float*)d_in[0];
    const float* mem    = (const float*)d_in[1];
    const float* ck1    = (const float*)d_in[2];
    const float* ck2    = (const float*)d_in[3];
    const float* cd1    = (const float*)d_in[4];
    const float* cd2    = (const float*)d_in[5];
    const float* ctx    = (const float*)d_in[6];
    const float* rec    = (const float*)d_in[7];
    const int*   px     = (const int*)d_in[8];
    const int*   py     = (const int*)d_in[9];
    float* out = (float*)d_out;

    // Order chosen so conv1 is the 4th launch (profiled this round).
    transpose_kernel<<<dim3(NPIX / 32, 3), dim3(32, 8)>>>(mem, out, 0);
    transpose_kernel<<<dim3(NPIX / 32, 3), dim3(32, 8)>>>(mem, out, 3);
    transpose_kernel<<<dim3(NPIX / 32, 2), dim3(32, 8)>>>(mem, out, 6);
    conv1_kernel<<<dim3(8, 16, C1SPLIT), 128>>>(mem, ck1);
    c1red_kernel<<<128, 256>>>();
    conv2_kernel<<<dim3(8, 31, 2), 128>>>(ck2);
    pool_kernel<<<(FLAT + 255) / 256, 256>>>();
    dense1_kernel<<<D1BLK, 256>>>(cd1);
    fuse1a_kernel<<<1, 1024>>>();
    fuse1b_kernel<<<9, 256>>>(inputs, cd2, ctx, rec);
    fuse1c_kernel<<<8, 256>>>(ctx);
    qsum_kernel<<<1, 256>>>();
    scores_kernel<<<NPIX / 8, 256>>>(mem);
    softmax_kernel<<<1, 1024>>>();
    ctpart_kernel<<<CTBLK, 256>>>(mem);
    final_kernel<<<1, 256>>>(mem, rec, px, py, out);
}

// round 13
// speedup vs baseline: 1.6596x; 1.0631x over previous
#include <cuda_runtime.h>
#include <cuda_bf16.h>

// ---------------------------------------------------------------------------
// NeuralMapCell pipeline, fp32. Round-12 + conv1 4px/thread + launch merges
// (c1red folded into conv2 loader; qsum folded into scores/final; transpose
// merged). dense1 is the 4th launch (profiled).
// Output: concat( c_t[256], r_t[256], new_mem[256*4096] )
// ---------------------------------------------------------------------------

#define H 64
#define W 64
#define UNITS 256
#define C1OC 32
#define C2OC 64
#define H2 62            // conv2 VALID output
#define HP 61            // pool output
#define FLAT (64*61*61)  // 238144
#define NPIX 4096
#define D1BLK 296
#define D1ROWS 805       // ceil(FLAT / D1BLK)
#define CTBLK 64
#define C1SPLIT 16
#define C1PITCH 20       // 16 ic + 4 pad floats (bank-spread LDS.128)
#define C2PITCH 20
#define C1Q (NPIX*C1OC)  // 131072 floats per ic-slice

// Scratch (device globals; no allocation allowed)
__device__ float g_c1p[C1SPLIT*C1Q];    // conv1 partials, [z][pixel][oc]
__device__ float g_c2p[2*C2OC*H2*H2];   // conv2 ic-half partials [z][oc][h][w]
__device__ float g_flat[FLAT];          // pooled activations [oc][h][w]
__device__ float g_part1[D1BLK*128];
__device__ float g_r128[128];
__device__ float g_rt[256];
__device__ float g_qpre[4*256];
__device__ float g_spre[4*256];
__device__ float g_qpart[8*256];
__device__ float g_scores[NPIX];
__device__ float g_expv[NPIX];
__device__ float g_invsum;
__device__ float g_partC[CTBLK*256];

// ---------------------------------------------------------------------------
// conv1: SAME 3x3, 256 -> 32 ch. Tile 8x8 px; grid (8,8,16); z = 16-ic slice.
// 128 threads, 4 px/thread: o4 = t&7 (oc quad), pg = t>>3 ->
//   row = pg>>2 (0..3, also row+4), col0 = (pg&3)*2.
// Per ic4: 4 LDS.128 + 4 LDG.128 weights + 64 FFMA, quad accumulators.
// ---------------------------------------------------------------------------
__global__ __launch_bounds__(128) void conv1_kernel(
    const float* __restrict__ mem, const float* __restrict__ w1)
{
    __shared__ float sa[100*C1PITCH];    // 10x10 px halo x 16 ic, 8 KB
    const int bw = blockIdx.x * 8;
    const int bh = blockIdx.y * 8;
    const int zic = blockIdx.z;          // ic slice (16 ch)
    const int t = threadIdx.x;

    for (int idx = t; idx < 100*4; idx += 128) {
        int p = idx >> 2;                // pixel 0..99
        int q = idx & 3;                 // f4 index within 16 ch
        int r = p / 10, c = p % 10;
        int h = bh + r - 1, w = bw + c - 1;
        float4 v = make_float4(0.f,0.f,0.f,0.f);
        if (h >= 0 && h < H && w >= 0 && w < W)
            v = reinterpret_cast<const float4*>(mem + (h*W + w)*UNITS + zic*16)[q];
        reinterpret_cast<float4*>(sa + p*C1PITCH)[q] = v;
    }
    __syncthreads();

    const int o4   = t & 7;
    const int pg   = t >> 3;             // 0..15
    const int row  = pg >> 2;            // 0..3 (and row+4)
    const int col0 = (pg & 3) * 2;       // 0,2,4,6
    float4 a00 = make_float4(0.f,0.f,0.f,0.f);
    float4 a01 = make_float4(0.f,0.f,0.f,0.f);
    float4 a10 = make_float4(0.f,0.f,0.f,0.f);
    float4 a11 = make_float4(0.f,0.f,0.f,0.f);

    #pragma unroll
    for (int kh = 0; kh < 3; kh++) {
        #pragma unroll
        for (int kw = 0; kw < 3; kw++) {
            const float* __restrict__ wp =
                w1 + ((size_t)((kh*3 + kw)*256 + zic*16))*32 + o4*4;
            const float* __restrict__ p00 =
                sa + ((row+kh)*10 + (col0+kw))*C1PITCH;
            const float* __restrict__ p10 = p00 + 4*10*C1PITCH;
            #pragma unroll
            for (int ic4 = 0; ic4 < 4; ic4++) {
                float4 v00 = *reinterpret_cast<const float4*>(p00 + ic4*4);
                float4 v01 = *reinterpret_cast<const float4*>(p00 + C1PITCH + ic4*4);
                float4 v10 = *reinterpret_cast<const float4*>(p10 + ic4*4);
                float4 v11 = *reinterpret_cast<const float4*>(p10 + C1PITCH + ic4*4);
                float4 w0 = __ldg(reinterpret_cast<const float4*>(wp + (4*ic4+0)*32));
                float4 wa = __ldg(reinterpret_cast<const float4*>(wp + (4*ic4+1)*32));
                float4 wb = __ldg(reinterpret_cast<const float4*>(wp + (4*ic4+2)*32));
                float4 wc = __ldg(reinterpret_cast<const float4*>(wp + (4*ic4+3)*32));
                a00.x += v00.x*w0.x + v00.y*wa.x + v00.z*wb.x + v00.w*wc.x;
                a00.y += v00.x*w0.y + v00.y*wa.y + v00.z*wb.y + v00.w*wc.y;
                a00.z += v00.x*w0.z + v00.y*wa.z + v00.z*wb.z + v00.w*wc.z;
                a00.w += v00.x*w0.w + v00.y*wa.w + v00.z*wb.w + v00.w*wc.w;
                a01.x += v01.x*w0.x + v01.y*wa.x + v01.z*wb.x + v01.w*wc.x;
                a01.y += v01.x*w0.y + v01.y*wa.y + v01.z*wb.y + v01.w*wc.y;
                a01.z += v01.x*w0.z + v01.y*wa.z + v01.z*wb.z + v01.w*wc.z;
                a01.w += v01.x*w0.w + v01.y*wa.w + v01.z*wb.w + v01.w*wc.w;
                a10.x += v10.x*w0.x + v10.y*wa.x + v10.z*wb.x + v10.w*wc.x;
                a10.y += v10.x*w0.y + v10.y*wa.y + v10.z*wb.y + v10.w*wc.y;
                a10.z += v10.x*w0.z + v10.y*wa.z + v10.z*wb.z + v10.w*wc.z;
                a10.w += v10.x*w0.w + v10.y*wa.w + v10.z*wb.w + v10.w*wc.w;
                a11.x += v11.x*w0.x + v11.y*wa.x + v11.z*wb.x + v11.w*wc.x;
                a11.y += v11.x*w0.y + v11.y*wa.y + v11.z*wb.y + v11.w*wc.y;
                a11.z += v11.x*w0.z + v11.y*wa.z + v11.z*wb.z + v11.w*wc.z;
                a11.w += v11.x*w0.w + v11.y*wa.w + v11.z*wb.w + v11.w*wc.w;
            }
        }
    }
    float* base = g_c1p + (size_t)zic*C1Q;
    const int pix00 = (bh + row)*W + (bw + col0);
    const int pix10 = (bh + row + 4)*W + (bw + col0);
    reinterpret_cast<float4*>(base + (size_t)pix00*C1OC)[o4] = a00;
    reinterpret_cast<float4*>(base + (size_t)(pix00+1)*C1OC)[o4] = a01;
    reinterpret_cast<float4*>(base + (size_t)pix10*C1OC)[o4] = a10;
    reinterpret_cast<float4*>(base + (size_t)(pix10+1)*C1OC)[o4] = a11;
}

// ---------------------------------------------------------------------------
// conv2: VALID 3x3, 32 -> 64 ch. Tile 2x8 px, ALL 64 oc; grid (8,31,2);
// z = ic half (16 ch). Loader sums the 16 conv1 ic-slice partials (c1red
// folded in). Inner loop validated round 10.
// ---------------------------------------------------------------------------
__global__ __launch_bounds__(128) void conv2_kernel(
    const float* __restrict__ w2)
{
    __shared__ float sa[40*C2PITCH];     // 4 rows x 10 cols x 16 ic, 3.2 KB
    const int bw = blockIdx.x * 8;
    const int bh = blockIdx.y * 2;
    const int zic = blockIdx.z;          // ic half (16 ch of conv1's 32 oc)
    const int t = threadIdx.x;

    for (int idx = t; idx < 40*4; idx += 128) {
        int p = idx >> 2;
        int q = idx & 3;
        int r = p / 10, c = p % 10;
        int h = bh + r, w = bw + c;
        float4 s = make_float4(0.f,0.f,0.f,0.f);
        if (h < H && w < W) {
            const size_t off = (size_t)(h*W + w)*C1OC + zic*16;
            #pragma unroll
            for (int z = 0; z < C1SPLIT; z++) {
                float4 v = __ldg(reinterpret_cast<const float4*>(
                    g_c1p + (size_t)z*C1Q + off) + q);
                s.x += v.x; s.y += v.y; s.z += v.z; s.w += v.w;
            }
        }
        reinterpret_cast<float4*>(sa + p*C2PITCH)[q] = s;
    }
    __syncthreads();

    const int o4   = t & 15;
    const int pp   = t >> 4;
    const int row  = pp >> 2;
    const int col0 = (pp & 3) * 2;
    float4 acc0 = make_float4(0.f,0.f,0.f,0.f);
    float4 acc1 = make_float4(0.f,0.f,0.f,0.f);

    #pragma unroll
    for (int kh = 0; kh < 3; kh++) {
        #pragma unroll
        for (int kw = 0; kw < 3; kw++) {
            const float* __restrict__ wp =
                w2 + ((size_t)((kh*3 + kw)*32 + zic*16))*64 + o4*4;
            const float* __restrict__ ap0 =
                sa + ((row+kh)*10 + (col0+kw))*C2PITCH;
            const float* __restrict__ ap1 = ap0 + C2PITCH;
            #pragma unroll
            for (int ic4 = 0; ic4 < 4; ic4++) {
                float4 a0 = *reinterpret_cast<const float4*>(ap0 + ic4*4);
                float4 a1 = *reinterpret_cast<const float4*>(ap1 + ic4*4);
                float4 w0 = __ldg(reinterpret_cast<const float4*>(wp + (4*ic4+0)*64));
                float4 wa = __ldg(reinterpret_cast<const float4*>(wp + (4*ic4+1)*64));
                float4 wb = __ldg(reinterpret_cast<const float4*>(wp + (4*ic4+2)*64));
                float4 wc = __ldg(reinterpret_cast<const float4*>(wp + (4*ic4+3)*64));
                acc0.x += a0.x*w0.x + a0.y*wa.x + a0.z*wb.x + a0.w*wc.x;
                acc0.y += a0.x*w0.y + a0.y*wa.y + a0.z*wb.y + a0.w*wc.y;
                acc0.z += a0.x*w0.z + a0.y*wa.z + a0.z*wb.z + a0.w*wc.z;
                acc0.w += a0.x*w0.w + a0.y*wa.w + a0.z*wb.w + a0.w*wc.w;
                acc1.x += a1.x*w0.x + a1.y*wa.x + a1.z*wb.x + a1.w*wc.x;
                acc1.y += a1.x*w0.y + a1.y*wa.y + a1.z*wb.y + a1.w*wc.y;
                acc1.z += a1.x*w0.z + a1.y*wa.z + a1.z*wb.z + a1.w*wc.z;
                acc1.w += a1.x*w0.w + a1.y*wa.w + a1.z*wb.w + a1.w*wc.w;
            }
        }
    }
    const int h2  = bh + row;
    const int oc0 = o4*4;
    const size_t zb = (size_t)zic*C2OC*H2*H2;
    #pragma unroll
    for (int s = 0; s < 2; s++) {
        int w2i = bw + col0 + s;
        if (w2i < H2) {
            float4 a = s ? acc1 : acc0;
            g_c2p[zb + (size_t)(oc0+0)*(H2*H2) + h2*H2 + w2i] = a.x;
            g_c2p[zb + (size_t)(oc0+1)*(H2*H2) + h2*H2 + w2i] = a.y;
            g_c2p[zb + (size_t)(oc0+2)*(H2*H2) + h2*H2 + w2i] = a.z;
            g_c2p[zb + (size_t)(oc0+3)*(H2*H2) + h2*H2 + w2i] = a.w;
        }
    }
}

// ---------------------------------------------------------------------------
// pool: sum the two conv2 ic-half partials, 2x2 sum pool * 0.25
// ---------------------------------------------------------------------------
__global__ __launch_bounds__(256) void pool_kernel()
{
    int idx = blockIdx.x * 256 + threadIdx.x;
    if (idx >= FLAT) return;
    int oc = idx / (HP*HP);
    int r = idx - oc*(HP*HP);
    int h = r / HP;
    int w = r - h*HP;
    const float* b0 = g_c2p + (size_t)oc*(H2*H2) + h*H2 + w;
    const float* b1 = b0 + (size_t)C2OC*H2*H2;
    g_flat[idx] = 0.25f * ((b0[0] + b1[0]) + (b0[1] + b1[1])
                         + (b0[H2] + b1[H2]) + (b0[H2+1] + b1[H2+1]));
}

// ---------------------------------------------------------------------------
// dense1: flat(1x238144) @ W1(238144x128). Per-lane float4 loads, 4-row
// unroll. (4th launch -> profiled this round)
// ---------------------------------------------------------------------------
__global__ __launch_bounds__(256) void dense1_kernel(const float* __restrict__ W1)
{
    const int t = threadIdx.x;
    const int lane = t & 31;
    const int wid  = t >> 5;
    const int row0 = blockIdx.x * D1ROWS;
    int lim = row0 + D1ROWS;
    if (lim > FLAT) lim = FLAT;

    float4 acc = make_float4(0.f,0.f,0.f,0.f);
    for (int k = 0; k < 104; k += 4) {          // 104*8 = 832 >= 805 rows
        #pragma unroll
        for (int u = 0; u < 4; u++) {
            int i = row0 + wid + 8*(k + u);
            if (i < lim) {
                float f = __ldg(g_flat + i);
                float4 wv = __ldg(reinterpret_cast<const float4*>(W1 + (size_t)i*128) + lane);
                acc.x += f*wv.x; acc.y += f*wv.y; acc.z += f*wv.z; acc.w += f*wv.w;
            }
        }
    }
    __shared__ float4 sred[256];
    sred[wid*32 + lane] = acc;
    __syncthreads();
    if (t < 32) {
        float4 s = sred[t];
        #pragma unroll
        for (int w = 1; w < 8; w++) {
            float4 v = sred[w*32 + t];
            s.x += v.x; s.y += v.y; s.z += v.z; s.w += v.w;
        }
        reinterpret_cast<float4*>(g_part1 + blockIdx.x*128)[t] = s;
    }
}

// ---------------------------------------------------------------------------
// Transpose memory (4096,256) -> new_mem region of out (single launch)
// ---------------------------------------------------------------------------
__global__ __launch_bounds__(256) void transpose_kernel(
    const float* __restrict__ mem, float* __restrict__ out)
{
    __shared__ float tile[32][33];
    const int p0 = blockIdx.x * 32;
    const int c0 = blockIdx.y * 32;
    const int tx = threadIdx.x, ty = threadIdx.y;
    #pragma unroll
    for (int j = ty; j < 32; j += 8)
        tile[j][tx] = mem[(p0 + j)*UNITS + c0 + tx];
    __syncthreads();
    #pragma unroll
    for (int j = ty; j < 32; j += 8)
        out[512 + (size_t)(c0 + j)*NPIX + p0 + tx] = tile[tx][j];
}

// ---------------------------------------------------------------------------
// fuse1a: reduce g_part1 (296x128) -> g_r128. 1024 threads, 8 slices per col.
// ---------------------------------------------------------------------------
__global__ __launch_bounds__(1024) void fuse1a_kernel()
{
    __shared__ float sred[1024];
    const int t = threadIdx.x;
    const int col = t & 127;
    const int sl  = t >> 7;              // 0..7
    float a = 0.f;
    #pragma unroll 4
    for (int b = sl*37; b < sl*37 + 37 && b < D1BLK; b++)
        a += g_part1[b*128 + col];
    sred[sl*128 + col] = a;
    __syncthreads();
    if (t < 128) {
        float s = 0.f;
        #pragma unroll
        for (int z = 0; z < 8; z++) s += sred[z*128 + t];
        g_r128[t] = s;
    }
}

// ---------------------------------------------------------------------------
// fuse1b: 9 blocks. b0: rt = r128@W2. b1-4: qpre z-partials (inputs@ctx).
// b5-8: spre z-partials (inputs@rec).
// ---------------------------------------------------------------------------
__global__ __launch_bounds__(256) void fuse1b_kernel(
    const float* __restrict__ inputs, const float* __restrict__ W2,
    const float* __restrict__ ctx, const float* __restrict__ rec)
{
    const int c = threadIdx.x;
    const int b = blockIdx.x;
    if (b == 0) {
        float rt = 0.f;
        #pragma unroll 8
        for (int k = 0; k < 128; k++)
            rt += g_r128[k] * __ldg(W2 + k*256 + c);
        g_rt[c] = rt;
    } else if (b <= 4) {
        const int z = b - 1;
        float q = 0.f;
        #pragma unroll 8
        for (int k = z*32; k < z*32 + 32; k++)
            q += __ldg(inputs + k) * __ldg(ctx + k*256 + c);
        g_qpre[z*256 + c] = q;
    } else {
        const int z = b - 5;
        float s = 0.f;
        #pragma unroll 8
        for (int k = z*32; k < z*32 + 32; k++)
            s += __ldg(inputs + k) * __ldg(rec + k*256 + c);
        g_spre[z*256 + c] = s;
    }
}

// ---------------------------------------------------------------------------
// fuse1c: 8 blocks, z-partials of rt@ctx[128:384]
// ---------------------------------------------------------------------------
__global__ __launch_bounds__(256) void fuse1c_kernel(const float* __restrict__ ctx)
{
    const int c = threadIdx.x;
    const int z = blockIdx.x;
    float q = 0.f;
    #pragma unroll 8
    for (int j = 0; j < 32; j++) {
        int k = z*32 + j;
        q += g_rt[k] * __ldg(ctx + (128 + k)*256 + c);
    }
    g_qpart[z*256 + c] = q;
}

// ---------------------------------------------------------------------------
// scores[p] = dot(q_t, memory[p,:]) — warp per row. q_t computed per-block
// from qpre/qpart partials (qsum folded in).
// ---------------------------------------------------------------------------
__global__ __launch_bounds__(256) void scores_kernel(const float* __restrict__ mem)
{
    __shared__ float sqf[256];
    const int t = threadIdx.x;
    {
        float q = 0.f;
        #pragma unroll
        for (int z = 0; z < 4; z++) q += __ldg(g_qpre + z*256 + t);
        #pragma unroll
        for (int z = 0; z < 8; z++) q += __ldg(g_qpart + z*256 + t);
        sqf[t] = q;
    }
    __syncthreads();

    const float4* sq = reinterpret_cast<const float4*>(sqf);
    const int lane = t & 31;
    const int p = blockIdx.x * 8 + (t >> 5);
    const float4* mp = reinterpret_cast<const float4*>(mem + p*UNITS);
    float4 m0 = mp[lane];
    float4 m1 = mp[lane + 32];
    float4 q0 = sq[lane];
    float4 q1 = sq[lane + 32];
    float acc = m0.x*q0.x + m0.y*q0.y + m0.z*q0.z + m0.w*q0.w
              + m1.x*q1.x + m1.y*q1.y + m1.z*q1.z + m1.w*q1.w;
    #pragma unroll
    for (int o = 16; o > 0; o >>= 1)
        acc += __shfl_down_sync(0xffffffffu, acc, o);
    if (lane == 0) g_scores[p] = acc;
}

// ---------------------------------------------------------------------------
// softmax over 4096 scores (single block)
// ---------------------------------------------------------------------------
__global__ __launch_bounds__(1024) void softmax_kernel()
{
    __shared__ float red[32];
    const int t = threadIdx.x;
    float4 v = reinterpret_cast<const float4*>(g_scores)[t];
    float m = fmaxf(fmaxf(v.x, v.y), fmaxf(v.z, v.w));
    #pragma unroll
    for (int o = 16; o > 0; o >>= 1)
        m = fmaxf(m, __shfl_xor_sync(0xffffffffu, m, o));
    if ((t & 31) == 0) red[t >> 5] = m;
    __syncthreads();
    if (t < 32) {
        float mm = red[t];
        #pragma unroll
        for (int o = 16; o > 0; o >>= 1)
            mm = fmaxf(mm, __shfl_xor_sync(0xffffffffu, mm, o));
        red[t] = mm;
    }
    __syncthreads();
    const float gmax = red[0];
    __syncthreads();

    float4 e;
    e.x = expf(v.x - gmax); e.y = expf(v.y - gmax);
    e.z = expf(v.z - gmax); e.w = expf(v.w - gmax);
    reinterpret_cast<float4*>(g_expv)[t] = e;
    float s = e.x + e.y + e.z + e.w;
    #pragma unroll
    for (int o = 16; o > 0; o >>= 1)
        s += __shfl_xor_sync(0xffffffffu, s, o);
    if ((t & 31) == 0) red[t >> 5] = s;
    __syncthreads();
    if (t == 0) {
        float ss = 0.f;
        for (int i = 0; i < 32; i++) ss += red[i];
        g_invsum = 1.f / ss;
    }
}

// ---------------------------------------------------------------------------
// c_t partials: sum_p expv[p] * memory[p,:], 64 blocks of 64 rows
// ---------------------------------------------------------------------------
__global__ __launch_bounds__(256) void ctpart_kernel(const float* __restrict__ mem)
{
    const int c = threadIdx.x;
    const int base = blockIdx.x * 64;
    float acc = 0.f;
    #pragma unroll 4
    for (int p = base; p < base + 64; p++)
        acc += g_expv[p] * __ldg(mem + p*UNITS + c);
    g_partC[blockIdx.x*256 + c] = acc;
}

// ---------------------------------------------------------------------------
// Final: reduce c_t; st from spre; importances; mem update at (x,y)
// ---------------------------------------------------------------------------
__global__ __launch_bounds__(256) void final_kernel(
    const float* __restrict__ mem, const float* __restrict__ rec,
    const int* __restrict__ px, const int* __restrict__ py,
    float* __restrict__ out)
{
    __shared__ float s_st[256], s_mold[256];
    __shared__ float red[16];
    __shared__ float s_frac;
    const int c = threadIdx.x;
    const int pos = px[0]*W + py[0];

    float ct = 0.f;
    #pragma unroll 8
    for (int b = 0; b < CTBLK; b++) ct += g_partC[b*256 + c];
    ct *= g_invsum;
    float rt = g_rt[c];
    float st = g_spre[c] + g_spre[256 + c] + g_spre[512 + c] + g_spre[768 + c];
    s_st[c] = st;
    s_mold[c] = mem[pos*UNITS + c];
    out[c] = ct;
    out[256 + c] = rt;

    float li = st * ct;
    float gi = st * rt;
    #pragma unroll
    for (int o = 16; o > 0; o >>= 1) {
        li += __shfl_xor_sync(0xffffffffu, li, o);
        gi += __shfl_xor_sync(0xffffffffu, gi, o);
    }
    if ((c & 31) == 0) {
        red[c >> 5] = li;
        red[8 + (c >> 5)] = gi;
    }
    __syncthreads();
    if (c == 0) {
        float L = 0.f, G = 0.f;
        for (int i = 0; i < 8; i++) { L += red[i]; G += red[8 + i]; }
        s_frac = L / (L + G);
    }
    __syncthreads();

    const float frac = s_frac;
    float d = 0.f;
    #pragma unroll 8
    for (int k = 0; k < 256; k++)
        d += (s_mold[k] - s_st[k]) * __ldg(rec + (128 + k)*256 + c);
    out[512 + (size_t)c*NPIX + pos] = s_mold[c] + frac * d;
}

// ---------------------------------------------------------------------------
extern "C" void kernel_launch(void* const* d_in, const int* in_sizes, int n_in,
                              void* d_out, int out_size)
{
    const float* inputs = (const float*)d_in[0];
    const float* mem    = (const float*)d_in[1];
    const float* ck1    = (const float*)d_in[2];
    const float* ck2    = (const float*)d_in[3];
    const float* cd1    = (const float*)d_in[4];
    const float* cd2    = (const float*)d_in[5];
    const float* ctx    = (const float*)d_in[6];
    const float* rec    = (const float*)d_in[7];
    const int*   px     = (const int*)d_in[8];
    const int*   py     = (const int*)d_in[9];
    float* out = (float*)d_out;

    // dense1 is the 4th launch (profiled this round).
    conv1_kernel<<<dim3(8, 8, C1SPLIT), 128>>>(mem, ck1);
    conv2_kernel<<<dim3(8, 31, 2), 128>>>(ck2);
    pool_kernel<<<(FLAT + 255) / 256, 256>>>();
    dense1_kernel<<<D1BLK, 256>>>(cd1);
    transpose_kernel<<<dim3(NPIX / 32, UNITS / 32), dim3(32, 8)>>>(mem, out);
    fuse1a_kernel<<<1, 1024>>>();
    fuse1b_kernel<<<9, 256>>>(inputs, cd2, ctx, rec);
    fuse1c_kernel<<<8, 256>>>(ctx);
    scores_kernel<<<NPIX / 8, 256>>>(mem);
    softmax_kernel<<<1, 1024>>>();
    ctpart_kernel<<<CTBLK, 256>>>(mem);
    final_kernel<<<1, 256>>>(mem, rec, px, py, out);
}

// round 14
// speedup vs baseline: 1.7514x; 1.0553x over previous
#include <cuda_runtime.h>
#include <cuda_bf16.h>

// ---------------------------------------------------------------------------
// NeuralMapCell pipeline, fp32. Round-13 + dense1 592-block/unroll-8
// (MLP doubling). dense1 is the 4th launch (profiled).
// Output: concat( c_t[256], r_t[256], new_mem[256*4096] )
// ---------------------------------------------------------------------------

#define H 64
#define W 64
#define UNITS 256
#define C1OC 32
#define C2OC 64
#define H2 62            // conv2 VALID output
#define HP 61            // pool output
#define FLAT (64*61*61)  // 238144
#define NPIX 4096
#define D1BLK 592
#define D1ROWS 403       // ceil(FLAT / D1BLK)
#define CTBLK 64
#define C1SPLIT 16
#define C1PITCH 20       // 16 ic + 4 pad floats (bank-spread LDS.128)
#define C2PITCH 20
#define C1Q (NPIX*C1OC)  // 131072 floats per ic-slice

// Scratch (device globals; no allocation allowed)
__device__ float g_c1p[C1SPLIT*C1Q];    // conv1 partials, [z][pixel][oc]
__device__ float g_c2p[2*C2OC*H2*H2];   // conv2 ic-half partials [z][oc][h][w]
__device__ float g_flat[FLAT];          // pooled activations [oc][h][w]
__device__ float g_part1[D1BLK*128];
__device__ float g_r128[128];
__device__ float g_rt[256];
__device__ float g_qpre[4*256];
__device__ float g_spre[4*256];
__device__ float g_qpart[8*256];
__device__ float g_scores[NPIX];
__device__ float g_expv[NPIX];
__device__ float g_invsum;
__device__ float g_partC[CTBLK*256];

// ---------------------------------------------------------------------------
// conv1: SAME 3x3, 256 -> 32 ch. Tile 8x8 px; grid (8,8,16); z = 16-ic slice.
// 128 threads, 4 px/thread. Per ic4: 4 LDS.128 + 4 LDG.128 + 64 FFMA.
// ---------------------------------------------------------------------------
__global__ __launch_bounds__(128) void conv1_kernel(
    const float* __restrict__ mem, const float* __restrict__ w1)
{
    __shared__ float sa[100*C1PITCH];    // 10x10 px halo x 16 ic, 8 KB
    const int bw = blockIdx.x * 8;
    const int bh = blockIdx.y * 8;
    const int zic = blockIdx.z;          // ic slice (16 ch)
    const int t = threadIdx.x;

    for (int idx = t; idx < 100*4; idx += 128) {
        int p = idx >> 2;                // pixel 0..99
        int q = idx & 3;                 // f4 index within 16 ch
        int r = p / 10, c = p % 10;
        int h = bh + r - 1, w = bw + c - 1;
        float4 v = make_float4(0.f,0.f,0.f,0.f);
        if (h >= 0 && h < H && w >= 0 && w < W)
            v = reinterpret_cast<const float4*>(mem + (h*W + w)*UNITS + zic*16)[q];
        reinterpret_cast<float4*>(sa + p*C1PITCH)[q] = v;
    }
    __syncthreads();

    const int o4   = t & 7;
    const int pg   = t >> 3;             // 0..15
    const int row  = pg >> 2;            // 0..3 (and row+4)
    const int col0 = (pg & 3) * 2;       // 0,2,4,6
    float4 a00 = make_float4(0.f,0.f,0.f,0.f);
    float4 a01 = make_float4(0.f,0.f,0.f,0.f);
    float4 a10 = make_float4(0.f,0.f,0.f,0.f);
    float4 a11 = make_float4(0.f,0.f,0.f,0.f);

    #pragma unroll
    for (int kh = 0; kh < 3; kh++) {
        #pragma unroll
        for (int kw = 0; kw < 3; kw++) {
            const float* __restrict__ wp =
                w1 + ((size_t)((kh*3 + kw)*256 + zic*16))*32 + o4*4;
            const float* __restrict__ p00 =
                sa + ((row+kh)*10 + (col0+kw))*C1PITCH;
            const float* __restrict__ p10 = p00 + 4*10*C1PITCH;
            #pragma unroll
            for (int ic4 = 0; ic4 < 4; ic4++) {
                float4 v00 = *reinterpret_cast<const float4*>(p00 + ic4*4);
                float4 v01 = *reinterpret_cast<const float4*>(p00 + C1PITCH + ic4*4);
                float4 v10 = *reinterpret_cast<const float4*>(p10 + ic4*4);
                float4 v11 = *reinterpret_cast<const float4*>(p10 + C1PITCH + ic4*4);
                float4 w0 = __ldg(reinterpret_cast<const float4*>(wp + (4*ic4+0)*32));
                float4 wa = __ldg(reinterpret_cast<const float4*>(wp + (4*ic4+1)*32));
                float4 wb = __ldg(reinterpret_cast<const float4*>(wp + (4*ic4+2)*32));
                float4 wc = __ldg(reinterpret_cast<const float4*>(wp + (4*ic4+3)*32));
                a00.x += v00.x*w0.x + v00.y*wa.x + v00.z*wb.x + v00.w*wc.x;
                a00.y += v00.x*w0.y + v00.y*wa.y + v00.z*wb.y + v00.w*wc.y;
                a00.z += v00.x*w0.z + v00.y*wa.z + v00.z*wb.z + v00.w*wc.z;
                a00.w += v00.x*w0.w + v00.y*wa.w + v00.z*wb.w + v00.w*wc.w;
                a01.x += v01.x*w0.x + v01.y*wa.x + v01.z*wb.x + v01.w*wc.x;
                a01.y += v01.x*w0.y + v01.y*wa.y + v01.z*wb.y + v01.w*wc.y;
                a01.z += v01.x*w0.z + v01.y*wa.z + v01.z*wb.z + v01.w*wc.z;
                a01.w += v01.x*w0.w + v01.y*wa.w + v01.z*wb.w + v01.w*wc.w;
                a10.x += v10.x*w0.x + v10.y*wa.x + v10.z*wb.x + v10.w*wc.x;
                a10.y += v10.x*w0.y + v10.y*wa.y + v10.z*wb.y + v10.w*wc.y;
                a10.z += v10.x*w0.z + v10.y*wa.z + v10.z*wb.z + v10.w*wc.z;
                a10.w += v10.x*w0.w + v10.y*wa.w + v10.z*wb.w + v10.w*wc.w;
                a11.x += v11.x*w0.x + v11.y*wa.x + v11.z*wb.x + v11.w*wc.x;
                a11.y += v11.x*w0.y + v11.y*wa.y + v11.z*wb.y + v11.w*wc.y;
                a11.z += v11.x*w0.z + v11.y*wa.z + v11.z*wb.z + v11.w*wc.z;
                a11.w += v11.x*w0.w + v11.y*wa.w + v11.z*wb.w + v11.w*wc.w;
            }
        }
    }
    float* base = g_c1p + (size_t)zic*C1Q;
    const int pix00 = (bh + row)*W + (bw + col0);
    const int pix10 = (bh + row + 4)*W + (bw + col0);
    reinterpret_cast<float4*>(base + (size_t)pix00*C1OC)[o4] = a00;
    reinterpret_cast<float4*>(base + (size_t)(pix00+1)*C1OC)[o4] = a01;
    reinterpret_cast<float4*>(base + (size_t)pix10*C1OC)[o4] = a10;
    reinterpret_cast<float4*>(base + (size_t)(pix10+1)*C1OC)[o4] = a11;
}

// ---------------------------------------------------------------------------
// conv2: VALID 3x3, 32 -> 64 ch. Tile 2x8 px, ALL 64 oc; grid (8,31,2);
// z = ic half (16 ch). Loader sums the 16 conv1 ic-slice partials.
// ---------------------------------------------------------------------------
__global__ __launch_bounds__(128) void conv2_kernel(
    const float* __restrict__ w2)
{
    __shared__ float sa[40*C2PITCH];     // 4 rows x 10 cols x 16 ic, 3.2 KB
    const int bw = blockIdx.x * 8;
    const int bh = blockIdx.y * 2;
    const int zic = blockIdx.z;          // ic half (16 ch of conv1's 32 oc)
    const int t = threadIdx.x;

    for (int idx = t; idx < 40*4; idx += 128) {
        int p = idx >> 2;
        int q = idx & 3;
        int r = p / 10, c = p % 10;
        int h = bh + r, w = bw + c;
        float4 s = make_float4(0.f,0.f,0.f,0.f);
        if (h < H && w < W) {
            const size_t off = (size_t)(h*W + w)*C1OC + zic*16;
            #pragma unroll
            for (int z = 0; z < C1SPLIT; z++) {
                float4 v = __ldg(reinterpret_cast<const float4*>(
                    g_c1p + (size_t)z*C1Q + off) + q);
                s.x += v.x; s.y += v.y; s.z += v.z; s.w += v.w;
            }
        }
        reinterpret_cast<float4*>(sa + p*C2PITCH)[q] = s;
    }
    __syncthreads();

    const int o4   = t & 15;
    const int pp   = t >> 4;
    const int row  = pp >> 2;
    const int col0 = (pp & 3) * 2;
    float4 acc0 = make_float4(0.f,0.f,0.f,0.f);
    float4 acc1 = make_float4(0.f,0.f,0.f,0.f);

    #pragma unroll
    for (int kh = 0; kh < 3; kh++) {
        #pragma unroll
        for (int kw = 0; kw < 3; kw++) {
            const float* __restrict__ wp =
                w2 + ((size_t)((kh*3 + kw)*32 + zic*16))*64 + o4*4;
            const float* __restrict__ ap0 =
                sa + ((row+kh)*10 + (col0+kw))*C2PITCH;
            const float* __restrict__ ap1 = ap0 + C2PITCH;
            #pragma unroll
            for (int ic4 = 0; ic4 < 4; ic4++) {
                float4 a0 = *reinterpret_cast<const float4*>(ap0 + ic4*4);
                float4 a1 = *reinterpret_cast<const float4*>(ap1 + ic4*4);
                float4 w0 = __ldg(reinterpret_cast<const float4*>(wp + (4*ic4+0)*64));
                float4 wa = __ldg(reinterpret_cast<const float4*>(wp + (4*ic4+1)*64));
                float4 wb = __ldg(reinterpret_cast<const float4*>(wp + (4*ic4+2)*64));
                float4 wc = __ldg(reinterpret_cast<const float4*>(wp + (4*ic4+3)*64));
                acc0.x += a0.x*w0.x + a0.y*wa.x + a0.z*wb.x + a0.w*wc.x;
                acc0.y += a0.x*w0.y + a0.y*wa.y + a0.z*wb.y + a0.w*wc.y;
                acc0.z += a0.x*w0.z + a0.y*wa.z + a0.z*wb.z + a0.w*wc.z;
                acc0.w += a0.x*w0.w + a0.y*wa.w + a0.z*wb.w + a0.w*wc.w;
                acc1.x += a1.x*w0.x + a1.y*wa.x + a1.z*wb.x + a1.w*wc.x;
                acc1.y += a1.x*w0.y + a1.y*wa.y + a1.z*wb.y + a1.w*wc.y;
                acc1.z += a1.x*w0.z + a1.y*wa.z + a1.z*wb.z + a1.w*wc.z;
                acc1.w += a1.x*w0.w + a1.y*wa.w + a1.z*wb.w + a1.w*wc.w;
            }
        }
    }
    const int h2  = bh + row;
    const int oc0 = o4*4;
    const size_t zb = (size_t)zic*C2OC*H2*H2;
    #pragma unroll
    for (int s = 0; s < 2; s++) {
        int w2i = bw + col0 + s;
        if (w2i < H2) {
            float4 a = s ? acc1 : acc0;
            g_c2p[zb + (size_t)(oc0+0)*(H2*H2) + h2*H2 + w2i] = a.x;
            g_c2p[zb + (size_t)(oc0+1)*(H2*H2) + h2*H2 + w2i] = a.y;
            g_c2p[zb + (size_t)(oc0+2)*(H2*H2) + h2*H2 + w2i] = a.z;
            g_c2p[zb + (size_t)(oc0+3)*(H2*H2) + h2*H2 + w2i] = a.w;
        }
    }
}

// ---------------------------------------------------------------------------
// pool: sum the two conv2 ic-half partials, 2x2 sum pool * 0.25
// ---------------------------------------------------------------------------
__global__ __launch_bounds__(256) void pool_kernel()
{
    int idx = blockIdx.x * 256 + threadIdx.x;
    if (idx >= FLAT) return;
    int oc = idx / (HP*HP);
    int r = idx - oc*(HP*HP);
    int h = r / HP;
    int w = r - h*HP;
    const float* b0 = g_c2p + (size_t)oc*(H2*H2) + h*H2 + w;
    const float* b1 = b0 + (size_t)C2OC*H2*H2;
    g_flat[idx] = 0.25f * ((b0[0] + b1[0]) + (b0[1] + b1[1])
                         + (b0[H2] + b1[H2]) + (b0[H2+1] + b1[H2+1]));
}

// ---------------------------------------------------------------------------
// dense1: flat(1x238144) @ W1(238144x128). 592 blocks (4 CTAs/SM), 8-row
// unroll -> 8 independent float4 weight loads in flight per thread.
// ---------------------------------------------------------------------------
__global__ __launch_bounds__(256) void dense1_kernel(const float* __restrict__ W1)
{
    const int t = threadIdx.x;
    const int lane = t & 31;
    const int wid  = t >> 5;
    const int row0 = blockIdx.x * D1ROWS;
    int lim = row0 + D1ROWS;
    if (lim > FLAT) lim = FLAT;

    float4 acc = make_float4(0.f,0.f,0.f,0.f);
    for (int k = 0; k < 56; k += 8) {           // 56*8 = 448 >= 403 rows
        #pragma unroll
        for (int u = 0; u < 8; u++) {
            int i = row0 + wid + 8*(k + u);
            if (i < lim) {
                float f = __ldg(g_flat + i);
                float4 wv = __ldg(reinterpret_cast<const float4*>(W1 + (size_t)i*128) + lane);
                acc.x += f*wv.x; acc.y += f*wv.y; acc.z += f*wv.z; acc.w += f*wv.w;
            }
        }
    }
    __shared__ float4 sred[256];
    sred[wid*32 + lane] = acc;
    __syncthreads();
    if (t < 32) {
        float4 s = sred[t];
        #pragma unroll
        for (int w = 1; w < 8; w++) {
            float4 v = sred[w*32 + t];
            s.x += v.x; s.y += v.y; s.z += v.z; s.w += v.w;
        }
        reinterpret_cast<float4*>(g_part1 + blockIdx.x*128)[t] = s;
    }
}

// ---------------------------------------------------------------------------
// Transpose memory (4096,256) -> new_mem region of out (single launch)
// ---------------------------------------------------------------------------
__global__ __launch_bounds__(256) void transpose_kernel(
    const float* __restrict__ mem, float* __restrict__ out)
{
    __shared__ float tile[32][33];
    const int p0 = blockIdx.x * 32;
    const int c0 = blockIdx.y * 32;
    const int tx = threadIdx.x, ty = threadIdx.y;
    #pragma unroll
    for (int j = ty; j < 32; j += 8)
        tile[j][tx] = mem[(p0 + j)*UNITS + c0 + tx];
    __syncthreads();
    #pragma unroll
    for (int j = ty; j < 32; j += 8)
        out[512 + (size_t)(c0 + j)*NPIX + p0 + tx] = tile[tx][j];
}

// ---------------------------------------------------------------------------
// fuse1a: reduce g_part1 (592x128) -> g_r128. 1024 threads, 8 slices of 74.
// ---------------------------------------------------------------------------
__global__ __launch_bounds__(1024) void fuse1a_kernel()
{
    __shared__ float sred[1024];
    const int t = threadIdx.x;
    const int col = t & 127;
    const int sl  = t >> 7;              // 0..7
    float a = 0.f;
    #pragma unroll 4
    for (int b = sl*74; b < sl*74 + 74; b++)
        a += g_part1[b*128 + col];
    sred[sl*128 + col] = a;
    __syncthreads();
    if (t < 128) {
        float s = 0.f;
        #pragma unroll
        for (int z = 0; z < 8; z++) s += sred[z*128 + t];
        g_r128[t] = s;
    }
}

// ---------------------------------------------------------------------------
// fuse1b: 9 blocks. b0: rt = r128@W2. b1-4: qpre z-partials (inputs@ctx).
// b5-8: spre z-partials (inputs@rec).
// ---------------------------------------------------------------------------
__global__ __launch_bounds__(256) void fuse1b_kernel(
    const float* __restrict__ inputs, const float* __restrict__ W2,
    const float* __restrict__ ctx, const float* __restrict__ rec)
{
    const int c = threadIdx.x;
    const int b = blockIdx.x;
    if (b == 0) {
        float rt = 0.f;
        #pragma unroll 8
        for (int k = 0; k < 128; k++)
            rt += g_r128[k] * __ldg(W2 + k*256 + c);
        g_rt[c] = rt;
    } else if (b <= 4) {
        const int z = b - 1;
        float q = 0.f;
        #pragma unroll 8
        for (int k = z*32; k < z*32 + 32; k++)
            q += __ldg(inputs + k) * __ldg(ctx + k*256 + c);
        g_qpre[z*256 + c] = q;
    } else {
        const int z = b - 5;
        float s = 0.f;
        #pragma unroll 8
        for (int k = z*32; k < z*32 + 32; k++)
            s += __ldg(inputs + k) * __ldg(rec + k*256 + c);
        g_spre[z*256 + c] = s;
    }
}

// ---------------------------------------------------------------------------
// fuse1c: 8 blocks, z-partials of rt@ctx[128:384]
// ---------------------------------------------------------------------------
__global__ __launch_bounds__(256) void fuse1c_kernel(const float* __restrict__ ctx)
{
    const int c = threadIdx.x;
    const int z = blockIdx.x;
    float q = 0.f;
    #pragma unroll 8
    for (int j = 0; j < 32; j++) {
        int k = z*32 + j;
        q += g_rt[k] * __ldg(ctx + (128 + k)*256 + c);
    }
    g_qpart[z*256 + c] = q;
}

// ---------------------------------------------------------------------------
// scores[p] = dot(q_t, memory[p,:]) — warp per row; q_t from partials.
// ---------------------------------------------------------------------------
__global__ __launch_bounds__(256) void scores_kernel(const float* __restrict__ mem)
{
    __shared__ float sqf[256];
    const int t = threadIdx.x;
    {
        float q = 0.f;
        #pragma unroll
        for (int z = 0; z < 4; z++) q += __ldg(g_qpre + z*256 + t);
        #pragma unroll
        for (int z = 0; z < 8; z++) q += __ldg(g_qpart + z*256 + t);
        sqf[t] = q;
    }
    __syncthreads();

    const float4* sq = reinterpret_cast<const float4*>(sqf);
    const int lane = t & 31;
    const int p = blockIdx.x * 8 + (t >> 5);
    const float4* mp = reinterpret_cast<const float4*>(mem + p*UNITS);
    float4 m0 = mp[lane];
    float4 m1 = mp[lane + 32];
    float4 q0 = sq[lane];
    float4 q1 = sq[lane + 32];
    float acc = m0.x*q0.x + m0.y*q0.y + m0.z*q0.z + m0.w*q0.w
              + m1.x*q1.x + m1.y*q1.y + m1.z*q1.z + m1.w*q1.w;
    #pragma unroll
    for (int o = 16; o > 0; o >>= 1)
        acc += __shfl_down_sync(0xffffffffu, acc, o);
    if (lane == 0) g_scores[p] = acc;
}

// ---------------------------------------------------------------------------
// softmax over 4096 scores (single block)
// ---------------------------------------------------------------------------
__global__ __launch_bounds__(1024) void softmax_kernel()
{
    __shared__ float red[32];
    const int t = threadIdx.x;
    float4 v = reinterpret_cast<const float4*>(g_scores)[t];
    float m = fmaxf(fmaxf(v.x, v.y), fmaxf(v.z, v.w));
    #pragma unroll
    for (int o = 16; o > 0; o >>= 1)
        m = fmaxf(m, __shfl_xor_sync(0xffffffffu, m, o));
    if ((t & 31) == 0) red[t >> 5] = m;
    __syncthreads();
    if (t < 32) {
        float mm = red[t];
        #pragma unroll
        for (int o = 16; o > 0; o >>= 1)
            mm = fmaxf(mm, __shfl_xor_sync(0xffffffffu, mm, o));
        red[t] = mm;
    }
    __syncthreads();
    const float gmax = red[0];
    __syncthreads();

    float4 e;
    e.x = expf(v.x - gmax); e.y = expf(v.y - gmax);
    e.z = expf(v.z - gmax); e.w = expf(v.w - gmax);
    reinterpret_cast<float4*>(g_expv)[t] = e;
    float s = e.x + e.y + e.z + e.w;
    #pragma unroll
    for (int o = 16; o > 0; o >>= 1)
        s += __shfl_xor_sync(0xffffffffu, s, o);
    if ((t & 31) == 0) red[t >> 5] = s;
    __syncthreads();
    if (t == 0) {
        float ss = 0.f;
        for (int i = 0; i < 32; i++) ss += red[i];
        g_invsum = 1.f / ss;
    }
}

// ---------------------------------------------------------------------------
// c_t partials: sum_p expv[p] * memory[p,:], 64 blocks of 64 rows
// ---------------------------------------------------------------------------
__global__ __launch_bounds__(256) void ctpart_kernel(const float* __restrict__ mem)
{
    const int c = threadIdx.x;
    const int base = blockIdx.x * 64;
    float acc = 0.f;
    #pragma unroll 4
    for (int p = base; p < base + 64; p++)
        acc += g_expv[p] * __ldg(mem + p*UNITS + c);
    g_partC[blockIdx.x*256 + c] = acc;
}

// ---------------------------------------------------------------------------
// Final: reduce c_t; st from spre; importances; mem update at (x,y)
// ---------------------------------------------------------------------------
__global__ __launch_bounds__(256) void final_kernel(
    const float* __restrict__ mem, const float* __restrict__ rec,
    const int* __restrict__ px, const int* __restrict__ py,
    float* __restrict__ out)
{
    __shared__ float s_st[256], s_mold[256];
    __shared__ float red[16];
    __shared__ float s_frac;
    const int c = threadIdx.x;
    const int pos = px[0]*W + py[0];

    float ct = 0.f;
    #pragma unroll 8
    for (int b = 0; b < CTBLK; b++) ct += g_partC[b*256 + c];
    ct *= g_invsum;
    float rt = g_rt[c];
    float st = g_spre[c] + g_spre[256 + c] + g_spre[512 + c] + g_spre[768 + c];
    s_st[c] = st;
    s_mold[c] = mem[pos*UNITS + c];
    out[c] = ct;
    out[256 + c] = rt;

    float li = st * ct;
    float gi = st * rt;
    #pragma unroll
    for (int o = 16; o > 0; o >>= 1) {
        li += __shfl_xor_sync(0xffffffffu, li, o);
        gi += __shfl_xor_sync(0xffffffffu, gi, o);
    }
    if ((c & 31) == 0) {
        red[c >> 5] = li;
        red[8 + (c >> 5)] = gi;
    }
    __syncthreads();
    if (c == 0) {
        float L = 0.f, G = 0.f;
        for (int i = 0; i < 8; i++) { L += red[i]; G += red[8 + i]; }
        s_frac = L / (L + G);
    }
    __syncthreads();

    const float frac = s_frac;
    float d = 0.f;
    #pragma unroll 8
    for (int k = 0; k < 256; k++)
        d += (s_mold[k] - s_st[k]) * __ldg(rec + (128 + k)*256 + c);
    out[512 + (size_t)c*NPIX + pos] = s_mold[c] + frac * d;
}

// ---------------------------------------------------------------------------
extern "C" void kernel_launch(void* const* d_in, const int* in_sizes, int n_in,
                              void* d_out, int out_size)
{
    const float* inputs = (const float*)d_in[0];
    const float* mem    = (const float*)d_in[1];
    const float* ck1    = (const float*)d_in[2];
    const float* ck2    = (const float*)d_in[3];
    const float* cd1    = (const float*)d_in[4];
    const float* cd2    = (const float*)d_in[5];
    const float* ctx    = (const float*)d_in[6];
    const float* rec    = (const float*)d_in[7];
    const int*   px     = (const int*)d_in[8];
    const int*   py     = (const int*)d_in[9];
    float* out = (float*)d_out;

    // dense1 is the 4th launch (profiled this round).
    conv1_kernel<<<dim3(8, 8, C1SPLIT), 128>>>(mem, ck1);
    conv2_kernel<<<dim3(8, 31, 2), 128>>>(ck2);
    pool_kernel<<<(FLAT + 255) / 256, 256>>>();
    dense1_kernel<<<D1BLK, 256>>>(cd1);
    transpose_kernel<<<dim3(NPIX / 32, UNITS / 32), dim3(32, 8)>>>(mem, out);
    fuse1a_kernel<<<1, 1024>>>();
    fuse1b_kernel<<<9, 256>>>(inputs, cd2, ctx, rec);
    fuse1c_kernel<<<8, 256>>>(ctx);
    scores_kernel<<<NPIX / 8, 256>>>(mem);
    softmax_kernel<<<1, 1024>>>();
    ctpart_kernel<<<CTBLK, 256>>>(mem);
    final_kernel<<<1, 256>>>(mem, rec, px, py, out);
}